// round 10
// baseline (speedup 1.0000x reference)
#include <cuda_runtime.h>
#include <cuda_fp16.h>
#include <math.h>
#include <stdint.h>

#define SEQ  4096
#define DIN  1024
#define DOUT 1024

// ---------------- scratch (__device__ globals, alloc-free rule) ----------------
__device__ __half g_inCatH[(size_t)SEQ * (3 * DIN)];    // [hi | hi | lo] of input
__device__ __half g_WqCTH[(size_t)DOUT * (3 * DIN)];    // [hi | lo | hi] of Wq^T
__device__ __half g_WkCTH[(size_t)DOUT * (3 * DIN)];
__device__ __half g_WvCTH[(size_t)DOUT * (3 * DIN)];
__device__ __half g_QCatH[(size_t)SEQ * (3 * DOUT)];    // [Qhi | Qhi | Qlo]
__device__ __half g_KCatH[(size_t)SEQ * (3 * DOUT)];    // [Khi | Klo | Khi]
__device__ float  g_V[(size_t)SEQ * DOUT];
__device__ __half g_VTH[(size_t)DOUT * SEQ];            // half(V^T)
__device__ float  g_S[(size_t)SEQ * SEQ];               // fp32 scores
__device__ __half g_PH[(size_t)SEQ * SEQ];              // half unnorm probs
__device__ float  g_invS[SEQ];                          // 1/rowsum
__device__ unsigned g_rowMax[SEQ];                      // monotone-keyed row max

#define KEY_NEG_INF 0x007FFFFFu

// ---------------- helpers ----------------
__device__ __forceinline__ unsigned fkey(float f) {
    unsigned b = __float_as_uint(f);
    return (b & 0x80000000u) ? ~b : (b | 0x80000000u);
}
__device__ __forceinline__ float funkey(unsigned k) {
    unsigned b = (k & 0x80000000u) ? (k & 0x7FFFFFFFu) : ~k;
    return __uint_as_float(b);
}
#define CP_ASYNC16(saddr, gaddr) \
    asm volatile("cp.async.cg.shared.global [%0], [%1], 16;" :: "r"(saddr), "l"(gaddr))
#define CP_COMMIT() asm volatile("cp.async.commit_group;" ::: "memory")
#define CP_WAIT_GROUP(n) asm volatile("cp.async.wait_group " #n ";" ::: "memory")

__device__ __forceinline__ uint32_t smem_u32(const void* p) {
    uint32_t a;
    asm("{ .reg .u64 t; cvta.to.shared.u64 t, %1; cvt.u32.u64 %0, t; }" : "=r"(a) : "l"(p));
    return a;
}
#define LDSM_X4(r0, r1, r2, r3, addr) \
    asm volatile("ldmatrix.sync.aligned.m8n8.x4.shared.b16 {%0,%1,%2,%3}, [%4];" \
                 : "=r"(r0), "=r"(r1), "=r"(r2), "=r"(r3) : "r"(addr))

// fp16 m16n8k16 mma, fp32 accum
__device__ __forceinline__ void mma_f16(float* d,
                                        uint32_t a0, uint32_t a1, uint32_t a2, uint32_t a3,
                                        uint32_t b0, uint32_t b1) {
    asm volatile("mma.sync.aligned.m16n8k16.row.col.f32.f16.f16.f32 "
                 "{%0,%1,%2,%3}, {%4,%5,%6,%7}, {%8,%9}, {%0,%1,%2,%3};"
                 : "+f"(d[0]), "+f"(d[1]), "+f"(d[2]), "+f"(d[3])
                 : "r"(a0), "r"(a1), "r"(a2), "r"(a3), "r"(b0), "r"(b1));
}
// fp16 m16n8k16 mma, fp16 accum (rate experiment)
__device__ __forceinline__ void mma_f16h(uint32_t* d,
                                         uint32_t a0, uint32_t a1, uint32_t a2, uint32_t a3,
                                         uint32_t b0, uint32_t b1) {
    asm volatile("mma.sync.aligned.m16n8k16.row.col.f16.f16.f16.f16 "
                 "{%0,%1}, {%2,%3,%4,%5}, {%6,%7}, {%0,%1};"
                 : "+r"(d[0]), "+r"(d[1])
                 : "r"(a0), "r"(a1), "r"(a2), "r"(a3), "r"(b0), "r"(b1));
}

// ---------------------------------------------------------------------------
// shared tile geometry for both GEMMs
// ---------------------------------------------------------------------------
#define PADH 40
#define OPH_HALFS (128 * PADH)
#define OPH_BYTES (OPH_HALFS * 2)         // 10240
#define STAGEH_BYTES (2 * OPH_BYTES)      // 20480
#define NSTAGE_H 4

// ---------------------------------------------------------------------------
// fp16 GEMM (f32 accum): C = alpha * A[M,K] @ B[N,K]^T
// CTA 128x128x32, 8 warps (2M x 4N), warp 64x32, 4-stage cp.async, ldmatrix.
// outMode: 0 plain f32 (optional rowScale), 1 split-cat A [hi|hi|lo] (half),
//          2 split-cat B [hi|lo|hi] (half)
// ---------------------------------------------------------------------------
__global__ void __launch_bounds__(256, 2)
h16_gemm(const __half* __restrict__ A, const __half* __restrict__ B,
         void* __restrict__ Cv, int Ntot, int Kd, int lda, int ldb,
         float alpha, int outMode, const float* __restrict__ rowScale)
{
    extern __shared__ __half smh[];
    const uint32_t sbase = smem_u32(smh);

    const int gx = gridDim.x, gy = gridDim.y;
    const int lin = blockIdx.y * gx + blockIdx.x;
    const int GROUP = 8;
    const int per = GROUP * gx;
    const int g = lin / per;
    const int rem = lin - g * per;
    const int rowsLeft = gy - g * GROUP;
    const int rows = (GROUP < rowsLeft) ? GROUP : rowsLeft;
    const int byi = g * GROUP + rem % rows;
    const int bxi = rem / rows;

    const int tid  = threadIdx.x;
    const int wid  = tid >> 5;
    const int lane = tid & 31;
    const int warpM = wid >> 2;
    const int warpN = wid & 3;
    const int gID  = lane >> 2;
    const int tig  = lane & 3;
    const int rowBase = byi * 128;
    const int colBase = bxi * 128;

    const int lt = lane >> 3;
    const int l7 = lane & 7;
    const int aOff = ((lt & 1) * 8 + l7) * PADH + (lt >> 1) * 8;
    const int bOff = ((lt >> 1) * 8 + l7) * PADH + (lt & 1) * 8;

    const int ldRow0 = tid >> 2;
    const int ldSeg  = tid & 3;

    auto load_stage = [&](int st, int k0) {
        const uint32_t sA = sbase + st * STAGEH_BYTES;
        const uint32_t sB = sA + OPH_BYTES;
#pragma unroll
        for (int i = 0; i < 2; i++) {
            const int row = ldRow0 + i * 64;
            CP_ASYNC16(sA + (row * PADH + ldSeg * 8) * 2,
                       A + (size_t)(rowBase + row) * lda + k0 + ldSeg * 8);
        }
#pragma unroll
        for (int i = 0; i < 2; i++) {
            const int row = ldRow0 + i * 64;
            CP_ASYNC16(sB + (row * PADH + ldSeg * 8) * 2,
                       B + (size_t)(colBase + row) * ldb + k0 + ldSeg * 8);
        }
    };

    float acc[4][4][4];
#pragma unroll
    for (int i = 0; i < 4; i++)
#pragma unroll
        for (int j = 0; j < 4; j++)
#pragma unroll
            for (int r = 0; r < 4; r++) acc[i][j][r] = 0.0f;

    const int NITER = Kd >> 5;

    load_stage(0, 0);  CP_COMMIT();
    load_stage(1, 32); CP_COMMIT();
    load_stage(2, 64); CP_COMMIT();

    for (int j = 0; j < NITER; j++) {
        CP_WAIT_GROUP(2);
        __syncthreads();
        if (j + 3 < NITER) load_stage((j + 3) & 3, (j + 3) * 32);
        CP_COMMIT();

        const uint32_t sA = sbase + (j & 3) * STAGEH_BYTES;
        const uint32_t sB = sA + OPH_BYTES;

#pragma unroll
        for (int s = 0; s < 2; s++) {
            uint32_t af[4][4];
#pragma unroll
            for (int i = 0; i < 4; i++) {
                const uint32_t addr = sA + (((warpM * 64 + i * 16) * PADH) + s * 16 + aOff) * 2;
                LDSM_X4(af[i][0], af[i][1], af[i][2], af[i][3], addr);
            }
            uint32_t bf[4][2];
#pragma unroll
            for (int p = 0; p < 2; p++) {
                const uint32_t addr = sB + (((warpN * 32 + p * 16) * PADH) + s * 16 + bOff) * 2;
                LDSM_X4(bf[2 * p][0], bf[2 * p][1], bf[2 * p + 1][0], bf[2 * p + 1][1], addr);
            }
#pragma unroll
            for (int i = 0; i < 4; i++)
#pragma unroll
                for (int jn = 0; jn < 4; jn++)
                    mma_f16(acc[i][jn], af[i][0], af[i][1], af[i][2], af[i][3],
                            bf[jn][0], bf[jn][1]);
        }
    }

#pragma unroll
    for (int i = 0; i < 4; i++) {
        const int r0 = rowBase + warpM * 64 + i * 16 + gID;
#pragma unroll
        for (int jn = 0; jn < 4; jn++) {
            const int c = colBase + warpN * 32 + jn * 8 + tig * 2;
#pragma unroll
            for (int half = 0; half < 2; half++) {
                const int r = r0 + half * 8;
                float2 v;
                v.x = acc[i][jn][half * 2 + 0];
                v.y = acc[i][jn][half * 2 + 1];
                if (outMode == 0) {
                    const float sc = rowScale ? (alpha * rowScale[r]) : alpha;
                    v.x *= sc; v.y *= sc;
                    *(float2*)((float*)Cv + (size_t)r * Ntot + c) = v;
                } else {
                    v.x *= alpha; v.y *= alpha;
                    __half2 h = __floats2half2_rn(v.x, v.y);
                    float2 hf = __half22float2(h);
                    __half2 l = __floats2half2_rn(v.x - hf.x, v.y - hf.y);
                    __half* row = (__half*)Cv + (size_t)r * (3 * Ntot) + c;
                    if (outMode == 1) {
                        *(__half2*)(row)            = h;
                        *(__half2*)(row + Ntot)     = h;
                        *(__half2*)(row + 2 * Ntot) = l;
                    } else {
                        *(__half2*)(row)            = h;
                        *(__half2*)(row + Ntot)     = l;
                        *(__half2*)(row + 2 * Ntot) = h;
                    }
                }
            }
        }
    }
}

// ---------------------------------------------------------------------------
// fp16 GEMM with fp16 ACCUM (rate experiment): C += alpha * A @ B^T,
// plus per-row max (monotone-key atomicMax) on the final C values.
// Same tile/pipeline geometry as h16_gemm.
// ---------------------------------------------------------------------------
__global__ void __launch_bounds__(256, 2)
h16_gemm_corr(const __half* __restrict__ A, const __half* __restrict__ B,
              float* __restrict__ C, int Ntot, int Kd, int lda, int ldb,
              float alpha, unsigned* __restrict__ rowMax)
{
    extern __shared__ __half smh[];
    const uint32_t sbase = smem_u32(smh);

    const int gx = gridDim.x, gy = gridDim.y;
    const int lin = blockIdx.y * gx + blockIdx.x;
    const int GROUP = 8;
    const int per = GROUP * gx;
    const int g = lin / per;
    const int rem = lin - g * per;
    const int rowsLeft = gy - g * GROUP;
    const int rows = (GROUP < rowsLeft) ? GROUP : rowsLeft;
    const int byi = g * GROUP + rem % rows;
    const int bxi = rem / rows;

    const int tid  = threadIdx.x;
    const int wid  = tid >> 5;
    const int lane = tid & 31;
    const int warpM = wid >> 2;
    const int warpN = wid & 3;
    const int gID  = lane >> 2;
    const int tig  = lane & 3;
    const int rowBase = byi * 128;
    const int colBase = bxi * 128;

    const int lt = lane >> 3;
    const int l7 = lane & 7;
    const int aOff = ((lt & 1) * 8 + l7) * PADH + (lt >> 1) * 8;
    const int bOff = ((lt >> 1) * 8 + l7) * PADH + (lt & 1) * 8;

    const int ldRow0 = tid >> 2;
    const int ldSeg  = tid & 3;

    auto load_stage = [&](int st, int k0) {
        const uint32_t sA = sbase + st * STAGEH_BYTES;
        const uint32_t sB = sA + OPH_BYTES;
#pragma unroll
        for (int i = 0; i < 2; i++) {
            const int row = ldRow0 + i * 64;
            CP_ASYNC16(sA + (row * PADH + ldSeg * 8) * 2,
                       A + (size_t)(rowBase + row) * lda + k0 + ldSeg * 8);
        }
#pragma unroll
        for (int i = 0; i < 2; i++) {
            const int row = ldRow0 + i * 64;
            CP_ASYNC16(sB + (row * PADH + ldSeg * 8) * 2,
                       B + (size_t)(colBase + row) * ldb + k0 + ldSeg * 8);
        }
    };

    uint32_t acc[4][4][2];              // fp16x2 accumulators
#pragma unroll
    for (int i = 0; i < 4; i++)
#pragma unroll
        for (int j = 0; j < 4; j++) { acc[i][j][0] = 0u; acc[i][j][1] = 0u; }

    const int NITER = Kd >> 5;

    load_stage(0, 0);  CP_COMMIT();
    load_stage(1, 32); CP_COMMIT();
    load_stage(2, 64); CP_COMMIT();

    for (int j = 0; j < NITER; j++) {
        CP_WAIT_GROUP(2);
        __syncthreads();
        if (j + 3 < NITER) load_stage((j + 3) & 3, (j + 3) * 32);
        CP_COMMIT();

        const uint32_t sA = sbase + (j & 3) * STAGEH_BYTES;
        const uint32_t sB = sA + OPH_BYTES;

#pragma unroll
        for (int s = 0; s < 2; s++) {
            uint32_t af[4][4];
#pragma unroll
            for (int i = 0; i < 4; i++) {
                const uint32_t addr = sA + (((warpM * 64 + i * 16) * PADH) + s * 16 + aOff) * 2;
                LDSM_X4(af[i][0], af[i][1], af[i][2], af[i][3], addr);
            }
            uint32_t bf[4][2];
#pragma unroll
            for (int p = 0; p < 2; p++) {
                const uint32_t addr = sB + (((warpN * 32 + p * 16) * PADH) + s * 16 + bOff) * 2;
                LDSM_X4(bf[2 * p][0], bf[2 * p][1], bf[2 * p + 1][0], bf[2 * p + 1][1], addr);
            }
#pragma unroll
            for (int i = 0; i < 4; i++)
#pragma unroll
                for (int jn = 0; jn < 4; jn++)
                    mma_f16h(acc[i][jn], af[i][0], af[i][1], af[i][2], af[i][3],
                             bf[jn][0], bf[jn][1]);
        }
    }

    // epilogue: C += alpha*corr; per-row max with shuffle reduce + atomicMax
#pragma unroll
    for (int i = 0; i < 4; i++) {
        const int r0 = rowBase + warpM * 64 + i * 16 + gID;
#pragma unroll
        for (int half = 0; half < 2; half++) {
            const int r = r0 + half * 8;
            float vmax = -INFINITY;
#pragma unroll
            for (int jn = 0; jn < 4; jn++) {
                const int c = colBase + warpN * 32 + jn * 8 + tig * 2;
                float2 corr = __half22float2(*(__half2*)&acc[i][jn][half]);
                float2 v = *(float2*)(C + (size_t)r * Ntot + c);
                v.x += alpha * corr.x;
                v.y += alpha * corr.y;
                *(float2*)(C + (size_t)r * Ntot + c) = v;
                vmax = fmaxf(vmax, fmaxf(v.x, v.y));
            }
            // reduce over the 4 tig lanes of this row
            vmax = fmaxf(vmax, __shfl_xor_sync(0xFFFFFFFFu, vmax, 1));
            vmax = fmaxf(vmax, __shfl_xor_sync(0xFFFFFFFFu, vmax, 2));
            if (tig == 0) atomicMax(rowMax + r, fkey(vmax));
        }
    }
}

// ---------------------------------------------------------------------------
// split-cat to half: in[R,C] f32 -> out[R,3C] half [hi|hi|lo]; also inits rowMax
// ---------------------------------------------------------------------------
__global__ void __launch_bounds__(256)
split_cat_h(const float* __restrict__ in, __half* __restrict__ out, int R, int C,
            unsigned* __restrict__ rowMax)
{
    int i = blockIdx.x * 256 + threadIdx.x;
    if (i < SEQ) rowMax[i] = KEY_NEG_INF;
    int n4 = R * C / 4;
    if (i >= n4) return;
    float4 v = ((const float4*)in)[i];
    __half2 h0 = __floats2half2_rn(v.x, v.y);
    __half2 h1 = __floats2half2_rn(v.z, v.w);
    float2 f0 = __half22float2(h0), f1 = __half22float2(h1);
    __half2 l0 = __floats2half2_rn(v.x - f0.x, v.y - f0.y);
    __half2 l1 = __floats2half2_rn(v.z - f1.x, v.w - f1.y);
    int e = i * 4;
    int r = e / C, c = e % C;
    __half* row = out + (size_t)r * (3 * C) + c;
    *(__half2*)(row)             = h0; *(__half2*)(row + 2)         = h1;
    *(__half2*)(row + C)         = h0; *(__half2*)(row + C + 2)     = h1;
    *(__half2*)(row + 2 * C)     = l0; *(__half2*)(row + 2 * C + 2) = l1;
}

// ---------------------------------------------------------------------------
// batched transpose + split-cat half (B mode) for the 3 weight matrices
// ---------------------------------------------------------------------------
__global__ void __launch_bounds__(256)
transpose_split_cat_h3(const float* __restrict__ W0, const float* __restrict__ W1,
                       const float* __restrict__ W2,
                       __half* __restrict__ O0, __half* __restrict__ O1,
                       __half* __restrict__ O2, int R, int Cc)
{
    const float* in  = (blockIdx.z == 0) ? W0 : (blockIdx.z == 1) ? W1 : W2;
    __half*      out = (blockIdx.z == 0) ? O0 : (blockIdx.z == 1) ? O1 : O2;

    __shared__ float t[32][33];
    const int tx = threadIdx.x, ty = threadIdx.y;
    const int cx = blockIdx.x * 32 + tx;
#pragma unroll
    for (int i = 0; i < 4; i++) {
        int r = blockIdx.y * 32 + ty + i * 8;
        t[ty + i * 8][tx] = in[(size_t)r * Cc + cx];
    }
    __syncthreads();
    const int ox = blockIdx.y * 32 + tx;
#pragma unroll
    for (int i = 0; i < 4; i++) {
        int oy = blockIdx.x * 32 + ty + i * 8;
        float v = t[tx][ty + i * 8];
        __half h = __float2half_rn(v);
        __half l = __float2half_rn(v - __half2float(h));
        __half* row = out + (size_t)oy * (3 * R) + ox;
        row[0]     = h;
        row[R]     = l;
        row[2 * R] = h;
    }
}

// ---------------------------------------------------------------------------
// transpose to half: V[R,Cc] f32 -> VT[Cc,R] half (PV operand)
// ---------------------------------------------------------------------------
__global__ void __launch_bounds__(256)
transpose_h(const float* __restrict__ in, __half* __restrict__ out, int R, int Cc)
{
    __shared__ float t[32][33];
    const int tx = threadIdx.x, ty = threadIdx.y;
    const int cx = blockIdx.x * 32 + tx;
#pragma unroll
    for (int i = 0; i < 4; i++) {
        int r = blockIdx.y * 32 + ty + i * 8;
        t[ty + i * 8][tx] = in[(size_t)r * Cc + cx];
    }
    __syncthreads();
    const int ox = blockIdx.y * 32 + tx;
#pragma unroll
    for (int i = 0; i < 4; i++) {
        int oy = blockIdx.x * 32 + ty + i * 8;
        out[(size_t)oy * R + ox] = __float2half_rn(t[tx][ty + i * 8]);
    }
}

// ---------------------------------------------------------------------------
// single-pass softmax: uses precomputed rowMax; writes half unnormalized
// exp(x - m), stores invSum[row].
// ---------------------------------------------------------------------------
__global__ void __launch_bounds__(256)
softmax1_kernel(const float* __restrict__ S, const unsigned* __restrict__ rowMaxKey,
                __half* __restrict__ P, float* __restrict__ invSum)
{
    __shared__ float red[256];
    const int tid = threadIdx.x;
    const float* p = S + (size_t)blockIdx.x * SEQ;
    __half* q = P + (size_t)blockIdx.x * SEQ;
    const float m = funkey(rowMaxKey[blockIdx.x]);

    float sum = 0.0f;
    for (int c = tid * 4; c < SEQ; c += 1024) {
        float4 v = *(const float4*)(p + c);
        __half2 e0 = __floats2half2_rn(expf(v.x - m), expf(v.y - m));
        __half2 e1 = __floats2half2_rn(expf(v.z - m), expf(v.w - m));
        *(__half2*)(q + c)     = e0;
        *(__half2*)(q + c + 2) = e1;
        float2 f0 = __half22float2(e0), f1 = __half22float2(e1);
        sum += f0.x + f0.y + f1.x + f1.y;
    }
    red[tid] = sum; __syncthreads();
    for (int s = 128; s > 0; s >>= 1) { if (tid < s) red[tid] += red[tid + s]; __syncthreads(); }
    if (tid == 0) invSum[blockIdx.x] = 1.0f / red[0];
}

// ---------------------------------------------------------------------------
extern "C" void kernel_launch(void* const* d_in, const int* in_sizes, int n_in,
                              void* d_out, int out_size)
{
    const float* input = (const float*)d_in[0];
    const float* Wq    = (const float*)d_in[1];
    const float* Wk    = (const float*)d_in[2];
    const float* Wv    = (const float*)d_in[3];
    float*       out   = (float*)d_out;

    __half *inCatH, *WqCTH, *WkCTH, *WvCTH, *QCatH, *KCatH, *VTH, *PH;
    float *V, *S, *invS;
    unsigned* rowMax;
    cudaGetSymbolAddress((void**)&inCatH, g_inCatH);
    cudaGetSymbolAddress((void**)&WqCTH,  g_WqCTH);
    cudaGetSymbolAddress((void**)&WkCTH,  g_WkCTH);
    cudaGetSymbolAddress((void**)&WvCTH,  g_WvCTH);
    cudaGetSymbolAddress((void**)&QCatH,  g_QCatH);
    cudaGetSymbolAddress((void**)&KCatH,  g_KCatH);
    cudaGetSymbolAddress((void**)&V,      g_V);
    cudaGetSymbolAddress((void**)&VTH,    g_VTH);
    cudaGetSymbolAddress((void**)&S,      g_S);
    cudaGetSymbolAddress((void**)&PH,     g_PH);
    cudaGetSymbolAddress((void**)&invS,   g_invS);
    cudaGetSymbolAddress((void**)&rowMax, g_rowMax);

    const int smemH = NSTAGE_H * STAGEH_BYTES;   // 81920
    cudaFuncSetAttribute(h16_gemm, cudaFuncAttributeMaxDynamicSharedMemorySize, smemH);
    cudaFuncSetAttribute(h16_gemm_corr, cudaFuncAttributeMaxDynamicSharedMemorySize, smemH);

    const float scale = 1.0f / 32.0f;   // 1/sqrt(1024)
    dim3 tb(32, 8);
    dim3 gProj(DOUT / 128, SEQ / 128);
    dim3 gS(SEQ / 128, SEQ / 128);

    // 1-2: staging (split_cat_h also re-inits rowMax each replay)
    transpose_split_cat_h3<<<dim3(DOUT / 32, DIN / 32, 3), tb>>>(
        Wq, Wk, Wv, WqCTH, WkCTH, WvCTH, DIN, DOUT);
    split_cat_h<<<(SEQ * DIN / 4 + 255) / 256, 256>>>(input, inCatH, SEQ, DIN, rowMax);

    // 3-4: Q, K projections (fp16 3-pass, f32 acc); epilogues emit split-cat
    h16_gemm<<<gProj, 256, smemH>>>(inCatH, WqCTH, QCatH, DOUT, 3 * DIN,
                                    3 * DIN, 3 * DIN, 1.0f, 1, nullptr);
    h16_gemm<<<gProj, 256, smemH>>>(inCatH, WkCTH, KCatH, DOUT, 3 * DIN,
                                    3 * DIN, 3 * DIN, 1.0f, 2, nullptr);

    // 5: scores hh pass: S = (Qhi @ Khi^T) * scale  (K=1024, f32 acc)
    h16_gemm<<<gS, 256, smemH>>>(QCatH, KCatH, S, SEQ, DIN,
                                 3 * DOUT, 3 * DOUT, scale, 0, nullptr);

    // 6 (profiled): scores corr pass: S += (Qhi@Klo^T + Qlo@Khi^T)*scale
    //    (K=2048, f16 acc) + per-row max
    h16_gemm_corr<<<gS, 256, smemH>>>(QCatH + DOUT, KCatH + DOUT, S, SEQ, 2 * DIN,
                                      3 * DOUT, 3 * DOUT, scale, rowMax);

    // 7: V projection (fp16 3-pass, f32 acc), 8: V^T half
    h16_gemm<<<gProj, 256, smemH>>>(inCatH, WvCTH, V, DOUT, 3 * DIN,
                                    3 * DIN, 3 * DIN, 1.0f, 0, nullptr);
    transpose_h<<<dim3(DOUT / 32, SEQ / 32), tb>>>(V, VTH, SEQ, DOUT);

    // 9: single-pass softmax (uses rowMax), 10: PV with fused normalization
    softmax1_kernel<<<SEQ, 256>>>(S, rowMax, PH, invS);
    h16_gemm<<<gProj, 256, smemH>>>(PH, VTH, out, DOUT, SEQ,
                                    SEQ, SEQ, 1.0f, 0, invS);
}

// round 11
// speedup vs baseline: 1.8418x; 1.8418x over previous
#include <cuda_runtime.h>
#include <cuda_fp16.h>
#include <math.h>
#include <stdint.h>

#define SEQ  4096
#define DIN  1024
#define DOUT 1024

// ---------------- scratch (__device__ globals, alloc-free rule) ----------------
__device__ __half g_inCat2[(size_t)SEQ * (2 * DIN)];   // [hi | hi] of input
__device__ __half g_WqTH[(size_t)DOUT * DIN];          // half((Wq - 1 a^T)^T)
__device__ __half g_WkTH[(size_t)DOUT * DIN];          // half((Wk - 1 b^T)^T)
__device__ __half g_WvCT2[(size_t)DOUT * (2 * DIN)];   // [hi | lo] of Wv^T
__device__ __half g_QH[(size_t)SEQ * DOUT];            // q~ (centered Q), half
__device__ __half g_KH[(size_t)SEQ * DOUT];            // k~ (centered K), half
__device__ float  g_V[(size_t)SEQ * DOUT];
__device__ __half g_VTH[(size_t)DOUT * SEQ];           // half(V^T)
__device__ float  g_S[(size_t)SEQ * SEQ];              // fp32 scores
__device__ __half g_PH[(size_t)SEQ * SEQ];             // half unnorm probs
__device__ float  g_invS[SEQ];                         // 1/rowsum
__device__ unsigned g_rowMax[SEQ];                     // monotone-keyed row max
__device__ float  g_a[DOUT], g_b[DOUT];                // col means of Wq, Wk
__device__ float  g_ab[1];                             // a . b
__device__ float  g_gq[DIN], g_gk[DIN];                // W~q b, W~k a (per input dim)
__device__ float  g_sRow[SEQ];                         // s_i = rowsum(input)
__device__ float  g_colAdd[SEQ];                       // ab*s_j + w_j
__device__ float  g_zRow[SEQ];                         // z_i

#define KEY_NEG_INF 0x007FFFFFu

// ---------------- helpers ----------------
__device__ __forceinline__ unsigned fkey(float f) {
    unsigned b = __float_as_uint(f);
    return (b & 0x80000000u) ? ~b : (b | 0x80000000u);
}
__device__ __forceinline__ float funkey(unsigned k) {
    unsigned b = (k & 0x80000000u) ? (k & 0x7FFFFFFFu) : ~k;
    return __uint_as_float(b);
}
#define CP_ASYNC16(saddr, gaddr) \
    asm volatile("cp.async.cg.shared.global [%0], [%1], 16;" :: "r"(saddr), "l"(gaddr))
#define CP_COMMIT() asm volatile("cp.async.commit_group;" ::: "memory")
#define CP_WAIT_GROUP(n) asm volatile("cp.async.wait_group " #n ";" ::: "memory")

__device__ __forceinline__ uint32_t smem_u32(const void* p) {
    uint32_t a;
    asm("{ .reg .u64 t; cvta.to.shared.u64 t, %1; cvt.u32.u64 %0, t; }" : "=r"(a) : "l"(p));
    return a;
}
#define LDSM_X4(r0, r1, r2, r3, addr) \
    asm volatile("ldmatrix.sync.aligned.m8n8.x4.shared.b16 {%0,%1,%2,%3}, [%4];" \
                 : "=r"(r0), "=r"(r1), "=r"(r2), "=r"(r3) : "r"(addr))

__device__ __forceinline__ void mma_f16(float* d,
                                        uint32_t a0, uint32_t a1, uint32_t a2, uint32_t a3,
                                        uint32_t b0, uint32_t b1) {
    asm volatile("mma.sync.aligned.m16n8k16.row.col.f32.f16.f16.f32 "
                 "{%0,%1,%2,%3}, {%4,%5,%6,%7}, {%8,%9}, {%0,%1,%2,%3};"
                 : "+f"(d[0]), "+f"(d[1]), "+f"(d[2]), "+f"(d[3])
                 : "r"(a0), "r"(a1), "r"(a2), "r"(a3), "r"(b0), "r"(b1));
}

// ---------------- tile geometry ----------------
#define PADH 40
#define OPH_HALFS (128 * PADH)
#define OPH_BYTES (OPH_HALFS * 2)
#define STAGEH_BYTES (2 * OPH_BYTES)
#define NSTAGE_H 4

// common GEMM body as a macro-free pattern: both kernels share identical mainloop.
#define GEMM_PROLOG()                                                              \
    extern __shared__ __half smh[];                                                \
    const uint32_t sbase = smem_u32(smh);                                          \
    const int gx = gridDim.x, gy = gridDim.y;                                      \
    const int lin = blockIdx.y * gx + blockIdx.x;                                  \
    const int GROUP = 8;                                                           \
    const int per = GROUP * gx;                                                    \
    const int g = lin / per;                                                       \
    const int rem = lin - g * per;                                                 \
    const int rowsLeft = gy - g * GROUP;                                           \
    const int rows = (GROUP < rowsLeft) ? GROUP : rowsLeft;                        \
    const int byi = g * GROUP + rem % rows;                                        \
    const int bxi = rem / rows;                                                    \
    const int tid  = threadIdx.x;                                                  \
    const int lane = tid & 31;                                                     \
    const int wid  = tid >> 5;                                                     \
    const int warpM = wid >> 2;                                                    \
    const int warpN = wid & 3;                                                     \
    const int gID  = lane >> 2;                                                    \
    const int tig  = lane & 3;                                                     \
    const int rowBase = byi * 128;                                                 \
    const int colBase = bxi * 128;                                                 \
    const int lt = lane >> 3;                                                      \
    const int l7 = lane & 7;                                                       \
    const int aOff = ((lt & 1) * 8 + l7) * PADH + (lt >> 1) * 8;                   \
    const int bOff = ((lt >> 1) * 8 + l7) * PADH + (lt & 1) * 8;                   \
    const int ldRow0 = tid >> 2;                                                   \
    const int ldSeg  = tid & 3;                                                    \
    auto load_stage = [&](int st, int k0) {                                        \
        const uint32_t sA = sbase + st * STAGEH_BYTES;                             \
        const uint32_t sB = sA + OPH_BYTES;                                        \
        _Pragma("unroll")                                                          \
        for (int i = 0; i < 2; i++) {                                              \
            const int row = ldRow0 + i * 64;                                       \
            CP_ASYNC16(sA + (row * PADH + ldSeg * 8) * 2,                          \
                       A + (size_t)(rowBase + row) * lda + k0 + ldSeg * 8);        \
        }                                                                          \
        _Pragma("unroll")                                                          \
        for (int i = 0; i < 2; i++) {                                              \
            const int row = ldRow0 + i * 64;                                       \
            CP_ASYNC16(sB + (row * PADH + ldSeg * 8) * 2,                          \
                       B + (size_t)(colBase + row) * ldb + k0 + ldSeg * 8);        \
        }                                                                          \
    };                                                                             \
    float acc[4][4][4];                                                            \
    _Pragma("unroll")                                                              \
    for (int i = 0; i < 4; i++)                                                    \
        _Pragma("unroll")                                                          \
        for (int j = 0; j < 4; j++)                                                \
            _Pragma("unroll")                                                      \
            for (int r = 0; r < 4; r++) acc[i][j][r] = 0.0f;                       \
    const int NITER = Kd >> 5;                                                     \
    load_stage(0, 0);  CP_COMMIT();                                                \
    load_stage(1, 32); CP_COMMIT();                                                \
    load_stage(2, 64); CP_COMMIT();                                                \
    for (int j = 0; j < NITER; j++) {                                              \
        CP_WAIT_GROUP(2);                                                          \
        __syncthreads();                                                           \
        if (j + 3 < NITER) load_stage((j + 3) & 3, (j + 3) * 32);                  \
        CP_COMMIT();                                                               \
        const uint32_t sA = sbase + (j & 3) * STAGEH_BYTES;                        \
        const uint32_t sB = sA + OPH_BYTES;                                        \
        _Pragma("unroll")                                                          \
        for (int s = 0; s < 2; s++) {                                              \
            uint32_t af[4][4];                                                     \
            _Pragma("unroll")                                                      \
            for (int i = 0; i < 4; i++) {                                          \
                const uint32_t addr = sA + (((warpM * 64 + i * 16) * PADH) + s * 16 + aOff) * 2; \
                LDSM_X4(af[i][0], af[i][1], af[i][2], af[i][3], addr);             \
            }                                                                      \
            uint32_t bf[4][2];                                                     \
            _Pragma("unroll")                                                      \
            for (int p = 0; p < 2; p++) {                                          \
                const uint32_t addr = sB + (((warpN * 32 + p * 16) * PADH) + s * 16 + bOff) * 2; \
                LDSM_X4(bf[2 * p][0], bf[2 * p][1], bf[2 * p + 1][0], bf[2 * p + 1][1], addr);  \
            }                                                                      \
            _Pragma("unroll")                                                      \
            for (int i = 0; i < 4; i++)                                            \
                _Pragma("unroll")                                                  \
                for (int jn = 0; jn < 4; jn++)                                     \
                    mma_f16(acc[i][jn], af[i][0], af[i][1], af[i][2], af[i][3],    \
                            bf[jn][0], bf[jn][1]);                                 \
        }                                                                          \
    }

// ---------------------------------------------------------------------------
// fp16 GEMM: outMode 0 = fp32 out (optional rowScale), 3 = plain half out
// ---------------------------------------------------------------------------
__global__ void __launch_bounds__(256, 2)
h16_gemm(const __half* __restrict__ A, const __half* __restrict__ B,
         void* __restrict__ Cv, int Ntot, int Kd, int lda, int ldb,
         float alpha, int outMode, const float* __restrict__ rowScale)
{
    GEMM_PROLOG()

#pragma unroll
    for (int i = 0; i < 4; i++) {
        const int r0 = rowBase + warpM * 64 + i * 16 + gID;
#pragma unroll
        for (int jn = 0; jn < 4; jn++) {
            const int c = colBase + warpN * 32 + jn * 8 + tig * 2;
#pragma unroll
            for (int half = 0; half < 2; half++) {
                const int r = r0 + half * 8;
                float2 v;
                v.x = acc[i][jn][half * 2 + 0];
                v.y = acc[i][jn][half * 2 + 1];
                if (outMode == 0) {
                    const float sc = rowScale ? (alpha * rowScale[r]) : alpha;
                    v.x *= sc; v.y *= sc;
                    *(float2*)((float*)Cv + (size_t)r * Ntot + c) = v;
                } else {  // plain half out
                    __half2 h = __floats2half2_rn(alpha * v.x, alpha * v.y);
                    *(__half2*)((__half*)Cv + (size_t)r * Ntot + c) = h;
                }
            }
        }
    }
}

// ---------------------------------------------------------------------------
// scores GEMM: S = scale*(q~ k~^T + s_i*colAdd_j + z_i*s_j), fused rowMax
// ---------------------------------------------------------------------------
__global__ void __launch_bounds__(256, 2)
h16_scores(const __half* __restrict__ A, const __half* __restrict__ B,
           float* __restrict__ Cv, int Ntot, int Kd, int lda, int ldb,
           float scale, const float* __restrict__ sRow,
           const float* __restrict__ colAdd, const float* __restrict__ zRow,
           unsigned* __restrict__ rowMax)
{
    GEMM_PROLOG()

#pragma unroll
    for (int i = 0; i < 4; i++) {
        const int r0 = rowBase + warpM * 64 + i * 16 + gID;
#pragma unroll
        for (int half = 0; half < 2; half++) {
            const int r = r0 + half * 8;
            const float sr = sRow[r];
            const float zr = zRow[r];
            float vmax = -INFINITY;
#pragma unroll
            for (int jn = 0; jn < 4; jn++) {
                const int c = colBase + warpN * 32 + jn * 8 + tig * 2;
                float2 v;
                v.x = scale * (acc[i][jn][half * 2 + 0] + sr * colAdd[c]     + zr * sRow[c]);
                v.y = scale * (acc[i][jn][half * 2 + 1] + sr * colAdd[c + 1] + zr * sRow[c + 1]);
                *(float2*)(Cv + (size_t)r * Ntot + c) = v;
                vmax = fmaxf(vmax, fmaxf(v.x, v.y));
            }
            vmax = fmaxf(vmax, __shfl_xor_sync(0xFFFFFFFFu, vmax, 1));
            vmax = fmaxf(vmax, __shfl_xor_sync(0xFFFFFFFFu, vmax, 2));
            if (tig == 0) atomicMax(rowMax + r, fkey(vmax));
        }
    }
}

// ---------------------------------------------------------------------------
// column means of Wq and Wk -> a[d], b[d]
// ---------------------------------------------------------------------------
__global__ void __launch_bounds__(256)
colmean2(const float* __restrict__ Wq, const float* __restrict__ Wk,
         float* __restrict__ a, float* __restrict__ b)
{
    const float* W = blockIdx.y ? Wk : Wq;
    float* o       = blockIdx.y ? b  : a;
    __shared__ float red[8][33];
    const int tx = threadIdx.x & 31, ty = threadIdx.x >> 5;
    const int col = blockIdx.x * 32 + tx;
    float acc = 0.0f;
    for (int r = ty; r < DIN; r += 8)
        acc += W[(size_t)r * DOUT + col];
    red[ty][tx] = acc;
    __syncthreads();
    if (ty == 0) {
        float s = 0.0f;
#pragma unroll
        for (int k = 0; k < 8; k++) s += red[k][tx];
        o[col] = s * (1.0f / DIN);
    }
}

// a . b
__global__ void __launch_bounds__(256)
dotab(const float* __restrict__ a, const float* __restrict__ b, float* __restrict__ ab)
{
    __shared__ float red[256];
    float p = 0.0f;
    for (int i = threadIdx.x; i < DOUT; i += 256) p += a[i] * b[i];
    red[threadIdx.x] = p; __syncthreads();
    for (int s = 128; s > 0; s >>= 1) { if (threadIdx.x < s) red[threadIdx.x] += red[threadIdx.x + s]; __syncthreads(); }
    if (threadIdx.x == 0) ab[0] = red[0];
}

// gq_c = (Wq b)_c - ab ; gk_c = (Wk a)_c - ab
__global__ void __launch_bounds__(256)
gvec(const float* __restrict__ Wq, const float* __restrict__ Wk,
     const float* __restrict__ a, const float* __restrict__ b,
     const float* __restrict__ ab, float* __restrict__ gq, float* __restrict__ gk)
{
    __shared__ float r1[256], r2[256];
    const int c = blockIdx.x;
    float pq = 0.0f, pk = 0.0f;
    for (int d = threadIdx.x; d < DOUT; d += 256) {
        pq += Wq[(size_t)c * DOUT + d] * b[d];
        pk += Wk[(size_t)c * DOUT + d] * a[d];
    }
    r1[threadIdx.x] = pq; r2[threadIdx.x] = pk; __syncthreads();
    for (int s = 128; s > 0; s >>= 1) {
        if (threadIdx.x < s) { r1[threadIdx.x] += r1[threadIdx.x + s]; r2[threadIdx.x] += r2[threadIdx.x + s]; }
        __syncthreads();
    }
    if (threadIdx.x == 0) { gq[c] = r1[0] - ab[0]; gk[c] = r2[0] - ab[0]; }
}

// per input row i: s_i, z_i = in.gq, w_i = in.gk ; colAdd_i = ab*s_i + w_i
__global__ void __launch_bounds__(256)
szvec(const float* __restrict__ in, const float* __restrict__ gq,
      const float* __restrict__ gk, const float* __restrict__ ab,
      float* __restrict__ sRow, float* __restrict__ colAdd, float* __restrict__ zRow)
{
    __shared__ float r1[256], r2[256], r3[256];
    const int i = blockIdx.x;
    const float* p = in + (size_t)i * DIN;
    float s = 0.0f, z = 0.0f, w = 0.0f;
    for (int c = threadIdx.x; c < DIN; c += 256) {
        float v = p[c];
        s += v; z += v * gq[c]; w += v * gk[c];
    }
    r1[threadIdx.x] = s; r2[threadIdx.x] = z; r3[threadIdx.x] = w; __syncthreads();
    for (int st = 128; st > 0; st >>= 1) {
        if (threadIdx.x < st) {
            r1[threadIdx.x] += r1[threadIdx.x + st];
            r2[threadIdx.x] += r2[threadIdx.x + st];
            r3[threadIdx.x] += r3[threadIdx.x + st];
        }
        __syncthreads();
    }
    if (threadIdx.x == 0) {
        sRow[i] = r1[0];
        zRow[i] = r2[0];
        colAdd[i] = ab[0] * r1[0] + r3[0];
    }
}

// in[R,C] f32 -> [hi | hi] half (row length 2C); also inits rowMax
__global__ void __launch_bounds__(256)
split_cat2_h(const float* __restrict__ in, __half* __restrict__ out, int R, int C,
             unsigned* __restrict__ rowMax)
{
    int i = blockIdx.x * 256 + threadIdx.x;
    if (i < SEQ) rowMax[i] = KEY_NEG_INF;
    int n4 = R * C / 4;
    if (i >= n4) return;
    float4 v = ((const float4*)in)[i];
    __half2 h0 = __floats2half2_rn(v.x, v.y);
    __half2 h1 = __floats2half2_rn(v.z, v.w);
    int e = i * 4;
    int r = e / C, c = e % C;
    __half* row = out + (size_t)r * (2 * C) + c;
    *(__half2*)(row)         = h0; *(__half2*)(row + 2)     = h1;
    *(__half2*)(row + C)     = h0; *(__half2*)(row + C + 2) = h1;
}

// batched weight transposes: z=0 Wq centered(a) -> half [D,C]; z=1 Wk centered(b);
// z=2 Wv -> [hi | lo] (row length 2R)
__global__ void __launch_bounds__(256)
transpose_w3(const float* __restrict__ Wq, const float* __restrict__ Wk,
             const float* __restrict__ Wv, const float* __restrict__ a,
             const float* __restrict__ b,
             __half* __restrict__ Oq, __half* __restrict__ Ok, __half* __restrict__ Ov,
             int R, int Cc)
{
    const int z = blockIdx.z;
    const float* in = (z == 0) ? Wq : (z == 1) ? Wk : Wv;
    const float* ctr = (z == 0) ? a : (z == 1) ? b : nullptr;

    __shared__ float t[32][33];
    const int tx = threadIdx.x, ty = threadIdx.y;
    const int cx = blockIdx.x * 32 + tx;            // d index
    const float sub = ctr ? ctr[cx] : 0.0f;
#pragma unroll
    for (int i = 0; i < 4; i++) {
        int r = blockIdx.y * 32 + ty + i * 8;       // c index
        t[ty + i * 8][tx] = in[(size_t)r * Cc + cx] - sub;
    }
    __syncthreads();
    const int ox = blockIdx.y * 32 + tx;            // c index
#pragma unroll
    for (int i = 0; i < 4; i++) {
        int oy = blockIdx.x * 32 + ty + i * 8;      // d index
        float v = t[tx][ty + i * 8];
        if (z == 2) {
            __half h = __float2half_rn(v);
            __half l = __float2half_rn(v - __half2float(h));
            __half* row = Ov + (size_t)oy * (2 * R) + ox;
            row[0] = h;
            row[R] = l;
        } else {
            __half* O = (z == 0) ? Oq : Ok;
            O[(size_t)oy * R + ox] = __float2half_rn(v);
        }
    }
}

// V[R,Cc] f32 -> VT[Cc,R] half
__global__ void __launch_bounds__(256)
transpose_h(const float* __restrict__ in, __half* __restrict__ out, int R, int Cc)
{
    __shared__ float t[32][33];
    const int tx = threadIdx.x, ty = threadIdx.y;
    const int cx = blockIdx.x * 32 + tx;
#pragma unroll
    for (int i = 0; i < 4; i++) {
        int r = blockIdx.y * 32 + ty + i * 8;
        t[ty + i * 8][tx] = in[(size_t)r * Cc + cx];
    }
    __syncthreads();
    const int ox = blockIdx.y * 32 + tx;
#pragma unroll
    for (int i = 0; i < 4; i++) {
        int oy = blockIdx.x * 32 + ty + i * 8;
        out[(size_t)oy * R + ox] = __float2half_rn(t[tx][ty + i * 8]);
    }
}

// single-pass softmax with precomputed rowMax -> half unnormalized P + invSum
__global__ void __launch_bounds__(256)
softmax1_kernel(const float* __restrict__ S, const unsigned* __restrict__ rowMaxKey,
                __half* __restrict__ P, float* __restrict__ invSum)
{
    __shared__ float red[256];
    const int tid = threadIdx.x;
    const float* p = S + (size_t)blockIdx.x * SEQ;
    __half* q = P + (size_t)blockIdx.x * SEQ;
    const float m = funkey(rowMaxKey[blockIdx.x]);

    float sum = 0.0f;
    for (int c = tid * 4; c < SEQ; c += 1024) {
        float4 v = *(const float4*)(p + c);
        __half2 e0 = __floats2half2_rn(expf(v.x - m), expf(v.y - m));
        __half2 e1 = __floats2half2_rn(expf(v.z - m), expf(v.w - m));
        *(__half2*)(q + c)     = e0;
        *(__half2*)(q + c + 2) = e1;
        float2 f0 = __half22float2(e0), f1 = __half22float2(e1);
        sum += f0.x + f0.y + f1.x + f1.y;
    }
    red[tid] = sum; __syncthreads();
    for (int s = 128; s > 0; s >>= 1) { if (tid < s) red[tid] += red[tid + s]; __syncthreads(); }
    if (tid == 0) invSum[blockIdx.x] = 1.0f / red[0];
}

// ---------------------------------------------------------------------------
extern "C" void kernel_launch(void* const* d_in, const int* in_sizes, int n_in,
                              void* d_out, int out_size)
{
    const float* input = (const float*)d_in[0];
    const float* Wq    = (const float*)d_in[1];
    const float* Wk    = (const float*)d_in[2];
    const float* Wv    = (const float*)d_in[3];
    float*       out   = (float*)d_out;

    __half *inCat2, *WqTH, *WkTH, *WvCT2, *QH, *KH, *VTH, *PH;
    float *V, *S, *invS, *a, *b, *ab, *gq, *gk, *sRow, *colAdd, *zRow;
    unsigned* rowMax;
    cudaGetSymbolAddress((void**)&inCat2, g_inCat2);
    cudaGetSymbolAddress((void**)&WqTH,   g_WqTH);
    cudaGetSymbolAddress((void**)&WkTH,   g_WkTH);
    cudaGetSymbolAddress((void**)&WvCT2,  g_WvCT2);
    cudaGetSymbolAddress((void**)&QH,     g_QH);
    cudaGetSymbolAddress((void**)&KH,     g_KH);
    cudaGetSymbolAddress((void**)&V,      g_V);
    cudaGetSymbolAddress((void**)&VTH,    g_VTH);
    cudaGetSymbolAddress((void**)&S,      g_S);
    cudaGetSymbolAddress((void**)&PH,     g_PH);
    cudaGetSymbolAddress((void**)&invS,   g_invS);
    cudaGetSymbolAddress((void**)&a,      g_a);
    cudaGetSymbolAddress((void**)&b,      g_b);
    cudaGetSymbolAddress((void**)&ab,     g_ab);
    cudaGetSymbolAddress((void**)&gq,     g_gq);
    cudaGetSymbolAddress((void**)&gk,     g_gk);
    cudaGetSymbolAddress((void**)&sRow,   g_sRow);
    cudaGetSymbolAddress((void**)&colAdd, g_colAdd);
    cudaGetSymbolAddress((void**)&zRow,   g_zRow);
    cudaGetSymbolAddress((void**)&rowMax, g_rowMax);

    const int smemH = NSTAGE_H * STAGEH_BYTES;   // 81920
    cudaFuncSetAttribute(h16_gemm,   cudaFuncAttributeMaxDynamicSharedMemorySize, smemH);
    cudaFuncSetAttribute(h16_scores, cudaFuncAttributeMaxDynamicSharedMemorySize, smemH);

    const float scale = 1.0f / 32.0f;   // 1/sqrt(1024)
    dim3 tb(32, 8);
    dim3 gProj(DOUT / 128, SEQ / 128);
    dim3 gS(SEQ / 128, SEQ / 128);

    // 1-3: rank-one machinery (a, b, ab, gq, gk)
    colmean2<<<dim3(DOUT / 32, 2), 256>>>(Wq, Wk, a, b);
    dotab<<<1, 256>>>(a, b, ab);
    gvec<<<DIN, 256>>>(Wq, Wk, a, b, ab, gq, gk);

    // 4-5: operand staging
    split_cat2_h<<<(SEQ * DIN / 4 + 255) / 256, 256>>>(input, inCat2, SEQ, DIN, rowMax);
    transpose_w3<<<dim3(DOUT / 32, DIN / 32, 3), tb>>>(
        Wq, Wk, Wv, a, b, WqTH, WkTH, WvCT2, DIN, DOUT);

    // 6-7: Q~, K~ projections (single-pass fp16, centered weights, half out)
    h16_gemm<<<gProj, 256, smemH>>>(inCat2, WqTH, QH, DOUT, DIN,
                                    2 * DIN, DIN, 1.0f, 3, nullptr);
    h16_gemm<<<gProj, 256, smemH>>>(inCat2, WkTH, KH, DOUT, DIN,
                                    2 * DIN, DIN, 1.0f, 3, nullptr);

    // 8: correction vectors (s, colAdd, z) — exact fp32
    szvec<<<SEQ, 256>>>(input, gq, gk, ab, sRow, colAdd, zRow);

    // 9-10: V projection (2-pass: [inh|inh] x [Wvh|Wvl]), V^T half
    h16_gemm<<<gProj, 256, smemH>>>(inCat2, WvCT2, V, DOUT, 2 * DIN,
                                    2 * DIN, 2 * DIN, 1.0f, 0, nullptr);
    transpose_h<<<dim3(DOUT / 32, SEQ / 32), tb>>>(V, VTH, SEQ, DOUT);

    // 11: scores = scale*(q~ k~^T + rank-3 correction), fused rowMax
    h16_scores<<<gS, 256, smemH>>>(QH, KH, S, SEQ, DIN, DIN, DIN,
                                   scale, sRow, colAdd, zRow, rowMax);

    // 12: single-pass softmax -> half P + invSum
    softmax1_kernel<<<SEQ, 256>>>(S, rowMax, PH, invS);

    // 13: out = (P @ V) * invSum[row]
    h16_gemm<<<gProj, 256, smemH>>>(PH, VTH, out, DOUT, SEQ,
                                    SEQ, SEQ, 1.0f, 0, invS);
}

// round 12
// speedup vs baseline: 1.9605x; 1.0645x over previous
#include <cuda_runtime.h>
#include <cuda_fp16.h>
#include <math.h>
#include <stdint.h>

#define SEQ  4096
#define DIN  1024
#define DOUT 1024

// ---------------- scratch (__device__ globals, alloc-free rule) ----------------
__device__ __half g_inH[(size_t)SEQ * DIN];            // half(input)
__device__ __half g_WallTH[(size_t)3 * DOUT * DIN];    // [W~q^T ; W~k^T ; W~v^T] half
__device__ __half g_QKVH[(size_t)SEQ * (3 * DOUT)];    // [q~ | k~ | v~] half
__device__ __half g_VTH[(size_t)DOUT * SEQ];           // half(v~^T)
__device__ float  g_S[(size_t)SEQ * SEQ];              // fp32 scores
__device__ __half g_PH[(size_t)SEQ * SEQ];             // half unnorm probs
__device__ float  g_invS[SEQ];                         // 1/rowsum
__device__ float  g_tRow[SEQ];                         // sum_j exp_j * s_j
__device__ unsigned g_rowMax[SEQ];                     // monotone-keyed row max
__device__ float  g_a[DOUT], g_b[DOUT], g_cv[DOUT];    // col means of Wq, Wk, Wv
__device__ float  g_ab[1];                             // a . b
__device__ float  g_gq[DIN], g_gk[DIN];                // (Wq b - ab), (Wk a - ab)
__device__ float  g_sRow[SEQ];                         // s_i = rowsum(input)
__device__ float  g_colAdd[SEQ];                       // ab*s_j + w_j
__device__ float  g_zRow[SEQ];                         // z_i

#define KEY_NEG_INF 0x007FFFFFu

// ---------------- helpers ----------------
__device__ __forceinline__ unsigned fkey(float f) {
    unsigned b = __float_as_uint(f);
    return (b & 0x80000000u) ? ~b : (b | 0x80000000u);
}
__device__ __forceinline__ float funkey(unsigned k) {
    unsigned b = (k & 0x80000000u) ? (k & 0x7FFFFFFFu) : ~k;
    return __uint_as_float(b);
}
#define CP_ASYNC16(saddr, gaddr) \
    asm volatile("cp.async.cg.shared.global [%0], [%1], 16;" :: "r"(saddr), "l"(gaddr))
#define CP_COMMIT() asm volatile("cp.async.commit_group;" ::: "memory")
#define CP_WAIT_GROUP(n) asm volatile("cp.async.wait_group " #n ";" ::: "memory")

__device__ __forceinline__ uint32_t smem_u32(const void* p) {
    uint32_t a;
    asm("{ .reg .u64 t; cvta.to.shared.u64 t, %1; cvt.u32.u64 %0, t; }" : "=r"(a) : "l"(p));
    return a;
}
#define LDSM_X4(r0, r1, r2, r3, addr) \
    asm volatile("ldmatrix.sync.aligned.m8n8.x4.shared.b16 {%0,%1,%2,%3}, [%4];" \
                 : "=r"(r0), "=r"(r1), "=r"(r2), "=r"(r3) : "r"(addr))

__device__ __forceinline__ void mma_f16(float* d,
                                        uint32_t a0, uint32_t a1, uint32_t a2, uint32_t a3,
                                        uint32_t b0, uint32_t b1) {
    asm volatile("mma.sync.aligned.m16n8k16.row.col.f32.f16.f16.f32 "
                 "{%0,%1,%2,%3}, {%4,%5,%6,%7}, {%8,%9}, {%0,%1,%2,%3};"
                 : "+f"(d[0]), "+f"(d[1]), "+f"(d[2]), "+f"(d[3])
                 : "r"(a0), "r"(a1), "r"(a2), "r"(a3), "r"(b0), "r"(b1));
}

// ---------------- tile geometry ----------------
#define PADH 40
#define OPH_HALFS (128 * PADH)
#define OPH_BYTES (OPH_HALFS * 2)
#define STAGEH_BYTES (2 * OPH_BYTES)
#define NSTAGE_H 4

// shared 128x128x32 fp16 mainloop (4-stage cp.async + ldmatrix)
#define GEMM_PROLOG()                                                              \
    extern __shared__ __half smh[];                                                \
    const uint32_t sbase = smem_u32(smh);                                          \
    const int gx = gridDim.x, gy = gridDim.y;                                      \
    const int lin = blockIdx.y * gx + blockIdx.x;                                  \
    const int GROUP = 8;                                                           \
    const int per = GROUP * gx;                                                    \
    const int g = lin / per;                                                       \
    const int rem = lin - g * per;                                                 \
    const int rowsLeft = gy - g * GROUP;                                           \
    const int rows = (GROUP < rowsLeft) ? GROUP : rowsLeft;                        \
    const int byi = g * GROUP + rem % rows;                                        \
    const int bxi = rem / rows;                                                    \
    const int tid  = threadIdx.x;                                                  \
    const int lane = tid & 31;                                                     \
    const int wid  = tid >> 5;                                                     \
    const int warpM = wid >> 2;                                                    \
    const int warpN = wid & 3;                                                     \
    const int gID  = lane >> 2;                                                    \
    const int tig  = lane & 3;                                                     \
    const int rowBase = byi * 128;                                                 \
    const int colBase = bxi * 128;                                                 \
    const int lt = lane >> 3;                                                      \
    const int l7 = lane & 7;                                                       \
    const int aOff = ((lt & 1) * 8 + l7) * PADH + (lt >> 1) * 8;                   \
    const int bOff = ((lt >> 1) * 8 + l7) * PADH + (lt & 1) * 8;                   \
    const int ldRow0 = tid >> 2;                                                   \
    const int ldSeg  = tid & 3;                                                    \
    auto load_stage = [&](int st, int k0) {                                        \
        const uint32_t sA = sbase + st * STAGEH_BYTES;                             \
        const uint32_t sB = sA + OPH_BYTES;                                        \
        _Pragma("unroll")                                                          \
        for (int i = 0; i < 2; i++) {                                              \
            const int row = ldRow0 + i * 64;                                       \
            CP_ASYNC16(sA + (row * PADH + ldSeg * 8) * 2,                          \
                       A + (size_t)(rowBase + row) * lda + k0 + ldSeg * 8);        \
        }                                                                          \
        _Pragma("unroll")                                                          \
        for (int i = 0; i < 2; i++) {                                              \
            const int row = ldRow0 + i * 64;                                       \
            CP_ASYNC16(sB + (row * PADH + ldSeg * 8) * 2,                          \
                       B + (size_t)(colBase + row) * ldb + k0 + ldSeg * 8);        \
        }                                                                          \
    };                                                                             \
    float acc[4][4][4];                                                            \
    _Pragma("unroll")                                                              \
    for (int i = 0; i < 4; i++)                                                    \
        _Pragma("unroll")                                                          \
        for (int j = 0; j < 4; j++)                                                \
            _Pragma("unroll")                                                      \
            for (int r = 0; r < 4; r++) acc[i][j][r] = 0.0f;                       \
    const int NITER = Kd >> 5;                                                     \
    load_stage(0, 0);  CP_COMMIT();                                                \
    load_stage(1, 32); CP_COMMIT();                                                \
    load_stage(2, 64); CP_COMMIT();                                                \
    for (int j = 0; j < NITER; j++) {                                              \
        CP_WAIT_GROUP(2);                                                          \
        __syncthreads();                                                           \
        if (j + 3 < NITER) load_stage((j + 3) & 3, (j + 3) * 32);                  \
        CP_COMMIT();                                                               \
        const uint32_t sA = sbase + (j & 3) * STAGEH_BYTES;                        \
        const uint32_t sB = sA + OPH_BYTES;                                        \
        _Pragma("unroll")                                                          \
        for (int s = 0; s < 2; s++) {                                              \
            uint32_t af[4][4];                                                     \
            _Pragma("unroll")                                                      \
            for (int i = 0; i < 4; i++) {                                          \
                const uint32_t addr = sA + (((warpM * 64 + i * 16) * PADH) + s * 16 + aOff) * 2; \
                LDSM_X4(af[i][0], af[i][1], af[i][2], af[i][3], addr);             \
            }                                                                      \
            uint32_t bf[4][2];                                                     \
            _Pragma("unroll")                                                      \
            for (int p = 0; p < 2; p++) {                                          \
                const uint32_t addr = sB + (((warpN * 32 + p * 16) * PADH) + s * 16 + bOff) * 2; \
                LDSM_X4(bf[2 * p][0], bf[2 * p][1], bf[2 * p + 1][0], bf[2 * p + 1][1], addr);  \
            }                                                                      \
            _Pragma("unroll")                                                      \
            for (int i = 0; i < 4; i++)                                            \
                _Pragma("unroll")                                                  \
                for (int jn = 0; jn < 4; jn++)                                     \
                    mma_f16(acc[i][jn], af[i][0], af[i][1], af[i][2], af[i][3],    \
                            bf[jn][0], bf[jn][1]);                                 \
        }                                                                          \
    }

// ---------------------------------------------------------------------------
// fp16 GEMM, half output: C = A @ B^T  (QKV combined projection)
// ---------------------------------------------------------------------------
__global__ void __launch_bounds__(256, 2)
h16_gemm_h(const __half* __restrict__ A, const __half* __restrict__ B,
           __half* __restrict__ Cv, int Ntot, int Kd, int lda, int ldb)
{
    GEMM_PROLOG()

#pragma unroll
    for (int i = 0; i < 4; i++) {
        const int r0 = rowBase + warpM * 64 + i * 16 + gID;
#pragma unroll
        for (int jn = 0; jn < 4; jn++) {
            const int c = colBase + warpN * 32 + jn * 8 + tig * 2;
#pragma unroll
            for (int half = 0; half < 2; half++) {
                const int r = r0 + half * 8;
                __half2 h = __floats2half2_rn(acc[i][jn][half * 2 + 0],
                                              acc[i][jn][half * 2 + 1]);
                *(__half2*)(Cv + (size_t)r * Ntot + c) = h;
            }
        }
    }
}

// ---------------------------------------------------------------------------
// scores GEMM: S = scale*(q~ k~^T + s_i*colAdd_j + z_i*s_j), fused rowMax
// ---------------------------------------------------------------------------
__global__ void __launch_bounds__(256, 2)
h16_scores(const __half* __restrict__ A, const __half* __restrict__ B,
           float* __restrict__ Cv, int Ntot, int Kd, int lda, int ldb,
           float scale, const float* __restrict__ sRow,
           const float* __restrict__ colAdd, const float* __restrict__ zRow,
           unsigned* __restrict__ rowMax)
{
    GEMM_PROLOG()

#pragma unroll
    for (int i = 0; i < 4; i++) {
        const int r0 = rowBase + warpM * 64 + i * 16 + gID;
#pragma unroll
        for (int half = 0; half < 2; half++) {
            const int r = r0 + half * 8;
            const float sr = sRow[r];
            const float zr = zRow[r];
            float vmax = -INFINITY;
#pragma unroll
            for (int jn = 0; jn < 4; jn++) {
                const int c = colBase + warpN * 32 + jn * 8 + tig * 2;
                float2 v;
                v.x = scale * (acc[i][jn][half * 2 + 0] + sr * colAdd[c]     + zr * sRow[c]);
                v.y = scale * (acc[i][jn][half * 2 + 1] + sr * colAdd[c + 1] + zr * sRow[c + 1]);
                *(float2*)(Cv + (size_t)r * Ntot + c) = v;
                vmax = fmaxf(vmax, fmaxf(v.x, v.y));
            }
            vmax = fmaxf(vmax, __shfl_xor_sync(0xFFFFFFFFu, vmax, 1));
            vmax = fmaxf(vmax, __shfl_xor_sync(0xFFFFFFFFu, vmax, 2));
            if (tig == 0) atomicMax(rowMax + r, fkey(vmax));
        }
    }
}

// ---------------------------------------------------------------------------
// PV GEMM: out = invS[r] * (P^ @ v~^T + tRow[r] * cv[c])   (exact rank-1 restore)
// ---------------------------------------------------------------------------
__global__ void __launch_bounds__(256, 2)
h16_pv(const __half* __restrict__ A, const __half* __restrict__ B,
       float* __restrict__ Cv, int Ntot, int Kd, int lda, int ldb,
       const float* __restrict__ invS, const float* __restrict__ tRow,
       const float* __restrict__ cvec)
{
    GEMM_PROLOG()

#pragma unroll
    for (int i = 0; i < 4; i++) {
        const int r0 = rowBase + warpM * 64 + i * 16 + gID;
#pragma unroll
        for (int jn = 0; jn < 4; jn++) {
            const int c = colBase + warpN * 32 + jn * 8 + tig * 2;
#pragma unroll
            for (int half = 0; half < 2; half++) {
                const int r = r0 + half * 8;
                const float sc = invS[r];
                const float tr = tRow[r];
                float2 v;
                v.x = sc * (acc[i][jn][half * 2 + 0] + tr * cvec[c]);
                v.y = sc * (acc[i][jn][half * 2 + 1] + tr * cvec[c + 1]);
                *(float2*)(Cv + (size_t)r * Ntot + c) = v;
            }
        }
    }
}

// ---------------------------------------------------------------------------
// column means of Wq, Wk, Wv -> a, b, cv
// ---------------------------------------------------------------------------
__global__ void __launch_bounds__(256)
colmean3(const float* __restrict__ Wq, const float* __restrict__ Wk,
         const float* __restrict__ Wv,
         float* __restrict__ a, float* __restrict__ b, float* __restrict__ cv)
{
    const float* W = (blockIdx.y == 0) ? Wq : (blockIdx.y == 1) ? Wk : Wv;
    float* o       = (blockIdx.y == 0) ? a  : (blockIdx.y == 1) ? b  : cv;
    __shared__ float red[8][33];
    const int tx = threadIdx.x & 31, ty = threadIdx.x >> 5;
    const int col = blockIdx.x * 32 + tx;
    float acc = 0.0f;
    for (int r = ty; r < DIN; r += 8)
        acc += W[(size_t)r * DOUT + col];
    red[ty][tx] = acc;
    __syncthreads();
    if (ty == 0) {
        float s = 0.0f;
#pragma unroll
        for (int k = 0; k < 8; k++) s += red[k][tx];
        o[col] = s * (1.0f / DIN);
    }
}

// a . b
__global__ void __launch_bounds__(256)
dotab(const float* __restrict__ a, const float* __restrict__ b, float* __restrict__ ab)
{
    __shared__ float red[256];
    float p = 0.0f;
    for (int i = threadIdx.x; i < DOUT; i += 256) p += a[i] * b[i];
    red[threadIdx.x] = p; __syncthreads();
    for (int s = 128; s > 0; s >>= 1) { if (threadIdx.x < s) red[threadIdx.x] += red[threadIdx.x + s]; __syncthreads(); }
    if (threadIdx.x == 0) ab[0] = red[0];
}

// gq_c = (Wq b)_c - ab ; gk_c = (Wk a)_c - ab
__global__ void __launch_bounds__(256)
gvec(const float* __restrict__ Wq, const float* __restrict__ Wk,
     const float* __restrict__ a, const float* __restrict__ b,
     const float* __restrict__ ab, float* __restrict__ gq, float* __restrict__ gk)
{
    __shared__ float r1[256], r2[256];
    const int c = blockIdx.x;
    float pq = 0.0f, pk = 0.0f;
    for (int d = threadIdx.x; d < DOUT; d += 256) {
        pq += Wq[(size_t)c * DOUT + d] * b[d];
        pk += Wk[(size_t)c * DOUT + d] * a[d];
    }
    r1[threadIdx.x] = pq; r2[threadIdx.x] = pk; __syncthreads();
    for (int s = 128; s > 0; s >>= 1) {
        if (threadIdx.x < s) { r1[threadIdx.x] += r1[threadIdx.x + s]; r2[threadIdx.x] += r2[threadIdx.x + s]; }
        __syncthreads();
    }
    if (threadIdx.x == 0) { gq[c] = r1[0] - ab[0]; gk[c] = r2[0] - ab[0]; }
}

// per input row i: s_i, z_i = in.gq, w_i = in.gk ; colAdd_i = ab*s_i + w_i
__global__ void __launch_bounds__(256)
szvec(const float* __restrict__ in, const float* __restrict__ gq,
      const float* __restrict__ gk, const float* __restrict__ ab,
      float* __restrict__ sRow, float* __restrict__ colAdd, float* __restrict__ zRow)
{
    __shared__ float r1[256], r2[256], r3[256];
    const int i = blockIdx.x;
    const float* p = in + (size_t)i * DIN;
    float s = 0.0f, z = 0.0f, w = 0.0f;
    for (int c = threadIdx.x; c < DIN; c += 256) {
        float v = p[c];
        s += v; z += v * gq[c]; w += v * gk[c];
    }
    r1[threadIdx.x] = s; r2[threadIdx.x] = z; r3[threadIdx.x] = w; __syncthreads();
    for (int st = 128; st > 0; st >>= 1) {
        if (threadIdx.x < st) {
            r1[threadIdx.x] += r1[threadIdx.x + st];
            r2[threadIdx.x] += r2[threadIdx.x + st];
            r3[threadIdx.x] += r3[threadIdx.x + st];
        }
        __syncthreads();
    }
    if (threadIdx.x == 0) {
        sRow[i] = r1[0];
        zRow[i] = r2[0];
        colAdd[i] = ab[0] * r1[0] + r3[0];
    }
}

// f32 -> half convert; also inits rowMax keys
__global__ void __launch_bounds__(256)
conv_h(const float* __restrict__ in, __half* __restrict__ out, int n4,
       unsigned* __restrict__ rowMax)
{
    int i = blockIdx.x * 256 + threadIdx.x;
    if (i < SEQ) rowMax[i] = KEY_NEG_INF;
    if (i >= n4) return;
    float4 v = ((const float4*)in)[i];
    __half2 h0 = __floats2half2_rn(v.x, v.y);
    __half2 h1 = __floats2half2_rn(v.z, v.w);
    *(__half2*)(out + i * 4)     = h0;
    *(__half2*)(out + i * 4 + 2) = h1;
}

// batched centered weight transposes into WallTH: region z rows [z*DOUT, (z+1)*DOUT)
__global__ void __launch_bounds__(256)
transpose_w3(const float* __restrict__ Wq, const float* __restrict__ Wk,
             const float* __restrict__ Wv, const float* __restrict__ a,
             const float* __restrict__ b, const float* __restrict__ cv,
             __half* __restrict__ Wall, int R, int Cc)
{
    const int z = blockIdx.z;
    const float* in  = (z == 0) ? Wq : (z == 1) ? Wk : Wv;
    const float* ctr = (z == 0) ? a : (z == 1) ? b : cv;

    __shared__ float t[32][33];
    const int tx = threadIdx.x, ty = threadIdx.y;
    const int cx = blockIdx.x * 32 + tx;            // d index (output col of W)
    const float sub = ctr[cx];
#pragma unroll
    for (int i = 0; i < 4; i++) {
        int r = blockIdx.y * 32 + ty + i * 8;       // k index
        t[ty + i * 8][tx] = in[(size_t)r * Cc + cx] - sub;
    }
    __syncthreads();
    const int ox = blockIdx.y * 32 + tx;            // k index
    __half* O = Wall + (size_t)z * DOUT * DIN;
#pragma unroll
    for (int i = 0; i < 4; i++) {
        int oy = blockIdx.x * 32 + ty + i * 8;      // d index
        O[(size_t)oy * R + ox] = __float2half_rn(t[tx][ty + i * 8]);
    }
}

// strided half transpose: in[j, d] (ld inLd, offset applied by caller) -> out[d, j]
__global__ void __launch_bounds__(256)
transpose_hh(const __half* __restrict__ in, __half* __restrict__ out, int R, int inLd)
{
    __shared__ __half t[32][34];
    const int tx = threadIdx.x, ty = threadIdx.y;
    const int cx = blockIdx.x * 32 + tx;            // d
#pragma unroll
    for (int i = 0; i < 4; i++) {
        int r = blockIdx.y * 32 + ty + i * 8;       // j
        t[ty + i * 8][tx] = in[(size_t)r * inLd + cx];
    }
    __syncthreads();
    const int ox = blockIdx.y * 32 + tx;            // j
#pragma unroll
    for (int i = 0; i < 4; i++) {
        int oy = blockIdx.x * 32 + ty + i * 8;      // d
        out[(size_t)oy * R + ox] = t[tx][ty + i * 8];
    }
}

// single-pass softmax: half unnorm P, invSum, and tRow = sum exp*s
__global__ void __launch_bounds__(256)
softmax1t_kernel(const float* __restrict__ S, const unsigned* __restrict__ rowMaxKey,
                 const float* __restrict__ sRow,
                 __half* __restrict__ P, float* __restrict__ invSum,
                 float* __restrict__ tRow)
{
    __shared__ float sS[SEQ];
    __shared__ float red[256], redT[256];
    const int tid = threadIdx.x;
    for (int c = tid; c < SEQ; c += 256) sS[c] = sRow[c];
    __syncthreads();

    const float* p = S + (size_t)blockIdx.x * SEQ;
    __half* q = P + (size_t)blockIdx.x * SEQ;
    const float m = funkey(rowMaxKey[blockIdx.x]);

    float sum = 0.0f, tsum = 0.0f;
    for (int c = tid * 4; c < SEQ; c += 1024) {
        float4 v = *(const float4*)(p + c);
        __half2 e0 = __floats2half2_rn(expf(v.x - m), expf(v.y - m));
        __half2 e1 = __floats2half2_rn(expf(v.z - m), expf(v.w - m));
        *(__half2*)(q + c)     = e0;
        *(__half2*)(q + c + 2) = e1;
        float2 f0 = __half22float2(e0), f1 = __half22float2(e1);
        sum  += f0.x + f0.y + f1.x + f1.y;
        tsum += f0.x * sS[c] + f0.y * sS[c + 1] + f1.x * sS[c + 2] + f1.y * sS[c + 3];
    }
    red[tid] = sum; redT[tid] = tsum; __syncthreads();
    for (int s = 128; s > 0; s >>= 1) {
        if (tid < s) { red[tid] += red[tid + s]; redT[tid] += redT[tid + s]; }
        __syncthreads();
    }
    if (tid == 0) {
        invSum[blockIdx.x] = 1.0f / red[0];
        tRow[blockIdx.x]   = redT[0];
    }
}

// ---------------------------------------------------------------------------
extern "C" void kernel_launch(void* const* d_in, const int* in_sizes, int n_in,
                              void* d_out, int out_size)
{
    const float* input = (const float*)d_in[0];
    const float* Wq    = (const float*)d_in[1];
    const float* Wk    = (const float*)d_in[2];
    const float* Wv    = (const float*)d_in[3];
    float*       out   = (float*)d_out;

    __half *inH, *WallTH, *QKVH, *VTH, *PH;
    float *S, *invS, *tRow, *a, *b, *cv, *ab, *gq, *gk, *sRow, *colAdd, *zRow;
    unsigned* rowMax;
    cudaGetSymbolAddress((void**)&inH,    g_inH);
    cudaGetSymbolAddress((void**)&WallTH, g_WallTH);
    cudaGetSymbolAddress((void**)&QKVH,   g_QKVH);
    cudaGetSymbolAddress((void**)&VTH,    g_VTH);
    cudaGetSymbolAddress((void**)&S,      g_S);
    cudaGetSymbolAddress((void**)&PH,     g_PH);
    cudaGetSymbolAddress((void**)&invS,   g_invS);
    cudaGetSymbolAddress((void**)&tRow,   g_tRow);
    cudaGetSymbolAddress((void**)&a,      g_a);
    cudaGetSymbolAddress((void**)&b,      g_b);
    cudaGetSymbolAddress((void**)&cv,     g_cv);
    cudaGetSymbolAddress((void**)&ab,     g_ab);
    cudaGetSymbolAddress((void**)&gq,     g_gq);
    cudaGetSymbolAddress((void**)&gk,     g_gk);
    cudaGetSymbolAddress((void**)&sRow,   g_sRow);
    cudaGetSymbolAddress((void**)&colAdd, g_colAdd);
    cudaGetSymbolAddress((void**)&zRow,   g_zRow);
    cudaGetSymbolAddress((void**)&rowMax, g_rowMax);

    const int smemH = NSTAGE_H * STAGEH_BYTES;   // 81920
    cudaFuncSetAttribute(h16_gemm_h, cudaFuncAttributeMaxDynamicSharedMemorySize, smemH);
    cudaFuncSetAttribute(h16_scores, cudaFuncAttributeMaxDynamicSharedMemorySize, smemH);
    cudaFuncSetAttribute(h16_pv,     cudaFuncAttributeMaxDynamicSharedMemorySize, smemH);

    const float scale = 1.0f / 32.0f;   // 1/sqrt(1024)
    dim3 tb(32, 8);
    dim3 gQKV(3 * DOUT / 128, SEQ / 128);   // 24 x 32
    dim3 gProj(DOUT / 128, SEQ / 128);
    dim3 gS(SEQ / 128, SEQ / 128);

    // rank-one machinery
    colmean3<<<dim3(DOUT / 32, 3), 256>>>(Wq, Wk, Wv, a, b, cv);
    dotab<<<1, 256>>>(a, b, ab);
    gvec<<<DIN, 256>>>(Wq, Wk, a, b, ab, gq, gk);

    // staging
    conv_h<<<(SEQ * DIN / 4 + 255) / 256, 256>>>(input, inH, SEQ * DIN / 4, rowMax);
    transpose_w3<<<dim3(DOUT / 32, DIN / 32, 3), tb>>>(
        Wq, Wk, Wv, a, b, cv, WallTH, DIN, DOUT);
    szvec<<<SEQ, 256>>>(input, gq, gk, ab, sRow, colAdd, zRow);

    // combined QKV projection: [q~|k~|v~] = inH @ WallTH^T  (single pass fp16)
    h16_gemm_h<<<gQKV, 256, smemH>>>(inH, WallTH, QKVH, 3 * DOUT, DIN,
                                     DIN, DIN);

    // v~^T (half, strided source)
    transpose_hh<<<dim3(DOUT / 32, SEQ / 32), tb>>>(QKVH + 2 * DOUT, VTH,
                                                    SEQ, 3 * DOUT);

    // scores = scale*(q~ k~^T + rank-3 correction), fused rowMax
    h16_scores<<<gS, 256, smemH>>>(QKVH, QKVH + DOUT, S, SEQ, DIN,
                                   3 * DOUT, 3 * DOUT,
                                   scale, sRow, colAdd, zRow, rowMax);

    // softmax (single pass): P^, invSum, tRow
    softmax1t_kernel<<<SEQ, 256>>>(S, rowMax, sRow, PH, invS, tRow);

    // out = invS * (P^ @ v~ + tRow * cv^T)
    h16_pv<<<gProj, 256, smemH>>>(PH, VTH, out, DOUT, SEQ, SEQ, SEQ,
                                  invS, tRow, cv);
}

// round 14
// speedup vs baseline: 2.0752x; 1.0585x over previous
#include <cuda_runtime.h>
#include <cuda_fp16.h>
#include <math.h>
#include <stdint.h>

#define SEQ  4096
#define DIN  1024
#define DOUT 1024

// ---------------- scratch (__device__ globals, alloc-free rule) ----------------
__device__ __half g_inH[(size_t)SEQ * DIN];            // half(input)
__device__ __half g_WallTH[(size_t)3 * DOUT * DIN];    // [W~q^T ; W~k^T ; W~v^T] half
__device__ __half g_QKVH[(size_t)SEQ * (3 * DOUT)];    // [q~ | k~ | v~] half
__device__ float  g_S[(size_t)SEQ * SEQ];              // fp32 scores
__device__ __half g_PH[(size_t)SEQ * SEQ];             // half unnorm probs
__device__ float  g_invS[SEQ];                         // 1/rowsum
__device__ float  g_tRow[SEQ];                         // sum_j exp_j * s_j
__device__ unsigned g_rowMax[SEQ];                     // monotone-keyed row max
__device__ float  g_a[DOUT], g_b[DOUT], g_cv[DOUT];    // col means of Wq, Wk, Wv
__device__ float  g_ab[1];                             // a . b
__device__ float  g_gq[DIN], g_gk[DIN];                // (Wq b - ab), (Wk a - ab)
__device__ float  g_sRow[SEQ];                         // s_i = rowsum(input)
__device__ float  g_colAdd[SEQ];                       // ab*s_j + w_j
__device__ float  g_zRow[SEQ];                         // z_i

#define KEY_NEG_INF 0x007FFFFFu

// ---------------- helpers ----------------
__device__ __forceinline__ unsigned fkey(float f) {
    unsigned b = __float_as_uint(f);
    return (b & 0x80000000u) ? ~b : (b | 0x80000000u);
}
__device__ __forceinline__ float funkey(unsigned k) {
    unsigned b = (k & 0x80000000u) ? (k & 0x7FFFFFFFu) : ~k;
    return __uint_as_float(b);
}
#define CP_ASYNC16(saddr, gaddr) \
    asm volatile("cp.async.cg.shared.global [%0], [%1], 16;" :: "r"(saddr), "l"(gaddr))
#define CP_COMMIT() asm volatile("cp.async.commit_group;" ::: "memory")
#define CP_WAIT_GROUP(n) asm volatile("cp.async.wait_group " #n ";" ::: "memory")

__device__ __forceinline__ uint32_t smem_u32(const void* p) {
    uint32_t a;
    asm("{ .reg .u64 t; cvta.to.shared.u64 t, %1; cvt.u32.u64 %0, t; }" : "=r"(a) : "l"(p));
    return a;
}
#define LDSM_X4(r0, r1, r2, r3, addr) \
    asm volatile("ldmatrix.sync.aligned.m8n8.x4.shared.b16 {%0,%1,%2,%3}, [%4];" \
                 : "=r"(r0), "=r"(r1), "=r"(r2), "=r"(r3) : "r"(addr))
#define LDSM_X4_T(r0, r1, r2, r3, addr) \
    asm volatile("ldmatrix.sync.aligned.m8n8.x4.trans.shared.b16 {%0,%1,%2,%3}, [%4];" \
                 : "=r"(r0), "=r"(r1), "=r"(r2), "=r"(r3) : "r"(addr))

__device__ __forceinline__ void mma_f16(float* d,
                                        uint32_t a0, uint32_t a1, uint32_t a2, uint32_t a3,
                                        uint32_t b0, uint32_t b1) {
    asm volatile("mma.sync.aligned.m16n8k16.row.col.f32.f16.f16.f32 "
                 "{%0,%1,%2,%3}, {%4,%5,%6,%7}, {%8,%9}, {%0,%1,%2,%3};"
                 : "+f"(d[0]), "+f"(d[1]), "+f"(d[2]), "+f"(d[3])
                 : "r"(a0), "r"(a1), "r"(a2), "r"(a3), "r"(b0), "r"(b1));
}

// ---------------- tile geometry ----------------
#define PADH 40
#define OPH_HALFS (128 * PADH)
#define OPH_BYTES (OPH_HALFS * 2)         // 10240
#define STAGEH_BYTES (2 * OPH_BYTES)      // 20480 (NT kernels: A + B)
#define NSTAGE_H 4
// NN B tile: 32 k-rows x 128 n, padded stride 136 halfs
#define PADB 136
#define OPB_BYTES (32 * PADB * 2)         // 8704
#define STAGE_PV (OPH_BYTES + OPB_BYTES)  // 18944

// shared 128x128x32 fp16 NT mainloop (4-stage cp.async + ldmatrix)
#define GEMM_PROLOG()                                                              \
    extern __shared__ __half smh[];                                                \
    const uint32_t sbase = smem_u32(smh);                                          \
    const int gx = gridDim.x, gy = gridDim.y;                                      \
    const int lin = blockIdx.y * gx + blockIdx.x;                                  \
    const int GROUP = 8;                                                           \
    const int per = GROUP * gx;                                                    \
    const int g = lin / per;                                                       \
    const int rem = lin - g * per;                                                 \
    const int rowsLeft = gy - g * GROUP;                                           \
    const int rows = (GROUP < rowsLeft) ? GROUP : rowsLeft;                        \
    const int byi = g * GROUP + rem % rows;                                        \
    const int bxi = rem / rows;                                                    \
    const int tid  = threadIdx.x;                                                  \
    const int lane = tid & 31;                                                     \
    const int wid  = tid >> 5;                                                     \
    const int warpM = wid >> 2;                                                    \
    const int warpN = wid & 3;                                                     \
    const int gID  = lane >> 2;                                                    \
    const int tig  = lane & 3;                                                     \
    const int rowBase = byi * 128;                                                 \
    const int colBase = bxi * 128;                                                 \
    const int lt = lane >> 3;                                                      \
    const int l7 = lane & 7;                                                       \
    const int aOff = ((lt & 1) * 8 + l7) * PADH + (lt >> 1) * 8;                   \
    const int bOff = ((lt >> 1) * 8 + l7) * PADH + (lt & 1) * 8;                   \
    const int ldRow0 = tid >> 2;                                                   \
    const int ldSeg  = tid & 3;                                                    \
    auto load_stage = [&](int st, int k0) {                                        \
        const uint32_t sA = sbase + st * STAGEH_BYTES;                             \
        const uint32_t sB = sA + OPH_BYTES;                                        \
        _Pragma("unroll")                                                          \
        for (int i = 0; i < 2; i++) {                                              \
            const int row = ldRow0 + i * 64;                                       \
            CP_ASYNC16(sA + (row * PADH + ldSeg * 8) * 2,                          \
                       A + (size_t)(rowBase + row) * lda + k0 + ldSeg * 8);        \
        }                                                                          \
        _Pragma("unroll")                                                          \
        for (int i = 0; i < 2; i++) {                                              \
            const int row = ldRow0 + i * 64;                                       \
            CP_ASYNC16(sB + (row * PADH + ldSeg * 8) * 2,                          \
                       B + (size_t)(colBase + row) * ldb + k0 + ldSeg * 8);        \
        }                                                                          \
    };                                                                             \
    float acc[4][4][4];                                                            \
    _Pragma("unroll")                                                              \
    for (int i = 0; i < 4; i++)                                                    \
        _Pragma("unroll")                                                          \
        for (int j = 0; j < 4; j++)                                                \
            _Pragma("unroll")                                                      \
            for (int r = 0; r < 4; r++) acc[i][j][r] = 0.0f;                       \
    const int NITER = Kd >> 5;                                                     \
    load_stage(0, 0);  CP_COMMIT();                                                \
    load_stage(1, 32); CP_COMMIT();                                                \
    load_stage(2, 64); CP_COMMIT();                                                \
    for (int j = 0; j < NITER; j++) {                                              \
        CP_WAIT_GROUP(2);                                                          \
        __syncthreads();                                                           \
        if (j + 3 < NITER) load_stage((j + 3) & 3, (j + 3) * 32);                  \
        CP_COMMIT();                                                               \
        const uint32_t sA = sbase + (j & 3) * STAGEH_BYTES;                        \
        const uint32_t sB = sA + OPH_BYTES;                                        \
        _Pragma("unroll")                                                          \
        for (int s = 0; s < 2; s++) {                                              \
            uint32_t af[4][4];                                                     \
            _Pragma("unroll")                                                      \
            for (int i = 0; i < 4; i++) {                                          \
                const uint32_t addr = sA + (((warpM * 64 + i * 16) * PADH) + s * 16 + aOff) * 2; \
                LDSM_X4(af[i][0], af[i][1], af[i][2], af[i][3], addr);             \
            }                                                                      \
            uint32_t bf[4][2];                                                     \
            _Pragma("unroll")                                                      \
            for (int p = 0; p < 2; p++) {                                          \
                const uint32_t addr = sB + (((warpN * 32 + p * 16) * PADH) + s * 16 + bOff) * 2; \
                LDSM_X4(bf[2 * p][0], bf[2 * p][1], bf[2 * p + 1][0], bf[2 * p + 1][1], addr);  \
            }                                                                      \
            _Pragma("unroll")                                                      \
            for (int i = 0; i < 4; i++)                                            \
                _Pragma("unroll")                                                  \
                for (int jn = 0; jn < 4; jn++)                                     \
                    mma_f16(acc[i][jn], af[i][0], af[i][1], af[i][2], af[i][3],    \
                            bf[jn][0], bf[jn][1]);                                 \
        }                                                                          \
    }

// ---------------------------------------------------------------------------
// fp16 GEMM, half output: C = A @ B^T  (QKV combined projection, NT)
// ---------------------------------------------------------------------------
__global__ void __launch_bounds__(256, 2)
h16_gemm_h(const __half* __restrict__ A, const __half* __restrict__ B,
           __half* __restrict__ Cv, int Ntot, int Kd, int lda, int ldb)
{
    GEMM_PROLOG()

#pragma unroll
    for (int i = 0; i < 4; i++) {
        const int r0 = rowBase + warpM * 64 + i * 16 + gID;
#pragma unroll
        for (int jn = 0; jn < 4; jn++) {
            const int c = colBase + warpN * 32 + jn * 8 + tig * 2;
#pragma unroll
            for (int half = 0; half < 2; half++) {
                const int r = r0 + half * 8;
                __half2 h = __floats2half2_rn(acc[i][jn][half * 2 + 0],
                                              acc[i][jn][half * 2 + 1]);
                *(__half2*)(Cv + (size_t)r * Ntot + c) = h;
            }
        }
    }
}

// ---------------------------------------------------------------------------
// scores GEMM (NT): S = scale*(q~ k~^T + s_i*colAdd_j + z_i*s_j), fused rowMax
// ---------------------------------------------------------------------------
__global__ void __launch_bounds__(256, 2)
h16_scores(const __half* __restrict__ A, const __half* __restrict__ B,
           float* __restrict__ Cv, int Ntot, int Kd, int lda, int ldb,
           float scale, const float* __restrict__ sRow,
           const float* __restrict__ colAdd, const float* __restrict__ zRow,
           unsigned* __restrict__ rowMax)
{
    GEMM_PROLOG()

#pragma unroll
    for (int i = 0; i < 4; i++) {
        const int r0 = rowBase + warpM * 64 + i * 16 + gID;
#pragma unroll
        for (int half = 0; half < 2; half++) {
            const int r = r0 + half * 8;
            const float sr = sRow[r];
            const float zr = zRow[r];
            float vmax = -INFINITY;
#pragma unroll
            for (int jn = 0; jn < 4; jn++) {
                const int c = colBase + warpN * 32 + jn * 8 + tig * 2;
                float2 v;
                v.x = scale * (acc[i][jn][half * 2 + 0] + sr * colAdd[c]     + zr * sRow[c]);
                v.y = scale * (acc[i][jn][half * 2 + 1] + sr * colAdd[c + 1] + zr * sRow[c + 1]);
                *(float2*)(Cv + (size_t)r * Ntot + c) = v;
                vmax = fmaxf(vmax, fmaxf(v.x, v.y));
            }
            vmax = fmaxf(vmax, __shfl_xor_sync(0xFFFFFFFFu, vmax, 1));
            vmax = fmaxf(vmax, __shfl_xor_sync(0xFFFFFFFFu, vmax, 2));
            if (tig == 0) atomicMax(rowMax + r, fkey(vmax));
        }
    }
}

// ---------------------------------------------------------------------------
// PV GEMM, NN form: out = invS[r]*(P^ @ B + tRow[r]*cv[c]); B = v~ rows j, cols d
// B tile loaded [32 k][128 n] (FULL: 2 cp.async/thread) via ldmatrix.trans.
// ---------------------------------------------------------------------------
__global__ void __launch_bounds__(256, 2)
h16_pv_nn(const __half* __restrict__ A, const __half* __restrict__ B,
          float* __restrict__ Cv, int Ntot, int Kd, int lda, int ldb,
          const float* __restrict__ invS, const float* __restrict__ tRow,
          const float* __restrict__ cvec)
{
    extern __shared__ __half smh[];
    const uint32_t sbase = smem_u32(smh);

    const int gx = gridDim.x, gy = gridDim.y;
    const int lin = blockIdx.y * gx + blockIdx.x;
    const int GROUP = 8;
    const int per = GROUP * gx;
    const int g = lin / per;
    const int rem = lin - g * per;
    const int rowsLeft = gy - g * GROUP;
    const int rows = (GROUP < rowsLeft) ? GROUP : rowsLeft;
    const int byi = g * GROUP + rem % rows;
    const int bxi = rem / rows;

    const int tid  = threadIdx.x;
    const int lane = tid & 31;
    const int wid  = tid >> 5;
    const int warpM = wid >> 2;
    const int warpN = wid & 3;
    const int gID  = lane >> 2;
    const int tig  = lane & 3;
    const int rowBase = byi * 128;
    const int colBase = bxi * 128;

    const int lt = lane >> 3;
    const int l7 = lane & 7;
    const int aOff  = ((lt & 1) * 8 + l7) * PADH + (lt >> 1) * 8;
    const int bOffT = ((lt & 1) * 8 + l7) * PADB + (lt >> 1) * 8;

    const int ldRow0 = tid >> 2;          // A: 0..63 (+64)
    const int ldSeg  = tid & 3;
    const int bRow   = tid >> 4;          // B: 0..15 (+16)
    const int bSeg   = tid & 15;          // 16 x 8-half segments = 128 cols

    auto load_stage = [&](int st, int k0) {
        const uint32_t sA = sbase + st * STAGE_PV;
        const uint32_t sB = sA + OPH_BYTES;
#pragma unroll
        for (int i = 0; i < 2; i++) {
            const int row = ldRow0 + i * 64;
            CP_ASYNC16(sA + (row * PADH + ldSeg * 8) * 2,
                       A + (size_t)(rowBase + row) * lda + k0 + ldSeg * 8);
        }
#pragma unroll
        for (int i = 0; i < 2; i++) {
            const int row = bRow + i * 16;
            CP_ASYNC16(sB + (row * PADB + bSeg * 8) * 2,
                       B + (size_t)(k0 + row) * ldb + colBase + bSeg * 8);
        }
    };

    float acc[4][4][4];
#pragma unroll
    for (int i = 0; i < 4; i++)
#pragma unroll
        for (int j = 0; j < 4; j++)
#pragma unroll
            for (int r = 0; r < 4; r++) acc[i][j][r] = 0.0f;

    const int NITER = Kd >> 5;

    load_stage(0, 0);  CP_COMMIT();
    load_stage(1, 32); CP_COMMIT();
    load_stage(2, 64); CP_COMMIT();

    for (int j = 0; j < NITER; j++) {
        CP_WAIT_GROUP(2);
        __syncthreads();
        if (j + 3 < NITER) load_stage((j + 3) & 3, (j + 3) * 32);
        CP_COMMIT();

        const uint32_t sA = sbase + (j & 3) * STAGE_PV;
        const uint32_t sB = sA + OPH_BYTES;

#pragma unroll
        for (int s = 0; s < 2; s++) {
            uint32_t af[4][4];
#pragma unroll
            for (int i = 0; i < 4; i++) {
                const uint32_t addr = sA + (((warpM * 64 + i * 16) * PADH) + s * 16 + aOff) * 2;
                LDSM_X4(af[i][0], af[i][1], af[i][2], af[i][3], addr);
            }
            uint32_t bf[4][2];
#pragma unroll
            for (int p = 0; p < 2; p++) {
                const uint32_t addr = sB +
                    ((s * 16) * PADB + warpN * 32 + p * 16 + bOffT) * 2;
                LDSM_X4_T(bf[2 * p][0], bf[2 * p][1], bf[2 * p + 1][0], bf[2 * p + 1][1], addr);
            }
#pragma unroll
            for (int i = 0; i < 4; i++)
#pragma unroll
                for (int jn = 0; jn < 4; jn++)
                    mma_f16(acc[i][jn], af[i][0], af[i][1], af[i][2], af[i][3],
                            bf[jn][0], bf[jn][1]);
        }
    }

#pragma unroll
    for (int i = 0; i < 4; i++) {
        const int r0 = rowBase + warpM * 64 + i * 16 + gID;
#pragma unroll
        for (int jn = 0; jn < 4; jn++) {
            const int c = colBase + warpN * 32 + jn * 8 + tig * 2;
#pragma unroll
            for (int half = 0; half < 2; half++) {
                const int r = r0 + half * 8;
                const float sc = invS[r];
                const float tr = tRow[r];
                float2 v;
                v.x = sc * (acc[i][jn][half * 2 + 0] + tr * cvec[c]);
                v.y = sc * (acc[i][jn][half * 2 + 1] + tr * cvec[c + 1]);
                *(float2*)(Cv + (size_t)r * Ntot + c) = v;
            }
        }
    }
}

// ---------------------------------------------------------------------------
// column means of Wq, Wk, Wv -> a, b, cv
// ---------------------------------------------------------------------------
__global__ void __launch_bounds__(256)
colmean3(const float* __restrict__ Wq, const float* __restrict__ Wk,
         const float* __restrict__ Wv,
         float* __restrict__ a, float* __restrict__ b, float* __restrict__ cv)
{
    const float* W = (blockIdx.y == 0) ? Wq : (blockIdx.y == 1) ? Wk : Wv;
    float* o       = (blockIdx.y == 0) ? a  : (blockIdx.y == 1) ? b  : cv;
    __shared__ float red[8][33];
    const int tx = threadIdx.x & 31, ty = threadIdx.x >> 5;
    const int col = blockIdx.x * 32 + tx;
    float acc = 0.0f;
    for (int r = ty; r < DIN; r += 8)
        acc += W[(size_t)r * DOUT + col];
    red[ty][tx] = acc;
    __syncthreads();
    if (ty == 0) {
        float s = 0.0f;
#pragma unroll
        for (int k = 0; k < 8; k++) s += red[k][tx];
        o[col] = s * (1.0f / DIN);
    }
}

// a . b
__global__ void __launch_bounds__(256)
dotab(const float* __restrict__ a, const float* __restrict__ b, float* __restrict__ ab)
{
    __shared__ float red[256];
    float p = 0.0f;
    for (int i = threadIdx.x; i < DOUT; i += 256) p += a[i] * b[i];
    red[threadIdx.x] = p; __syncthreads();
    for (int s = 128; s > 0; s >>= 1) { if (threadIdx.x < s) red[threadIdx.x] += red[threadIdx.x + s]; __syncthreads(); }
    if (threadIdx.x == 0) ab[0] = red[0];
}

// gq_c = (Wq b)_c - ab ; gk_c = (Wk a)_c - ab
__global__ void __launch_bounds__(256)
gvec(const float* __restrict__ Wq, const float* __restrict__ Wk,
     const float* __restrict__ a, const float* __restrict__ b,
     const float* __restrict__ ab, float* __restrict__ gq, float* __restrict__ gk)
{
    __shared__ float r1[256], r2[256];
    const int c = blockIdx.x;
    float pq = 0.0f, pk = 0.0f;
    for (int d = threadIdx.x; d < DOUT; d += 256) {
        pq += Wq[(size_t)c * DOUT + d] * b[d];
        pk += Wk[(size_t)c * DOUT + d] * a[d];
    }
    r1[threadIdx.x] = pq; r2[threadIdx.x] = pk; __syncthreads();
    for (int s = 128; s > 0; s >>= 1) {
        if (threadIdx.x < s) { r1[threadIdx.x] += r1[threadIdx.x + s]; r2[threadIdx.x] += r2[threadIdx.x + s]; }
        __syncthreads();
    }
    if (threadIdx.x == 0) { gq[c] = r1[0] - ab[0]; gk[c] = r2[0] - ab[0]; }
}

// per input row i: s_i, z_i = in.gq, w_i = in.gk ; colAdd_i = ab*s_i + w_i
__global__ void __launch_bounds__(256)
szvec(const float* __restrict__ in, const float* __restrict__ gq,
      const float* __restrict__ gk, const float* __restrict__ ab,
      float* __restrict__ sRow, float* __restrict__ colAdd, float* __restrict__ zRow)
{
    __shared__ float r1[256], r2[256], r3[256];
    const int i = blockIdx.x;
    const float* p = in + (size_t)i * DIN;
    float s = 0.0f, z = 0.0f, w = 0.0f;
    for (int c = threadIdx.x; c < DIN; c += 256) {
        float v = p[c];
        s += v; z += v * gq[c]; w += v * gk[c];
    }
    r1[threadIdx.x] = s; r2[threadIdx.x] = z; r3[threadIdx.x] = w; __syncthreads();
    for (int st = 128; st > 0; st >>= 1) {
        if (threadIdx.x < st) {
            r1[threadIdx.x] += r1[threadIdx.x + st];
            r2[threadIdx.x] += r2[threadIdx.x + st];
            r3[threadIdx.x] += r3[threadIdx.x + st];
        }
        __syncthreads();
    }
    if (threadIdx.x == 0) {
        sRow[i] = r1[0];
        zRow[i] = r2[0];
        colAdd[i] = ab[0] * r1[0] + r3[0];
    }
}

// f32 -> half convert, 4 independent float4 loads per thread; inits rowMax
__global__ void __launch_bounds__(256)
conv_h(const float* __restrict__ in, __half* __restrict__ out, int n4,
       unsigned* __restrict__ rowMax)
{
    const int t = blockIdx.x * 256 + threadIdx.x;
    const int chunk = gridDim.x * 256;
    if (t < SEQ) rowMax[t] = KEY_NEG_INF;
    const float4* in4 = (const float4*)in;
    float4 v0 = in4[t];
    float4 v1 = in4[t + chunk];
    float4 v2 = in4[t + 2 * chunk];
    float4 v3 = in4[t + 3 * chunk];
    __half2* o2 = (__half2*)out;
#pragma unroll
    for (int u = 0; u < 4; u++) {
        float4 v = (u == 0) ? v0 : (u == 1) ? v1 : (u == 2) ? v2 : v3;
        const int idx = t + u * chunk;
        o2[idx * 2]     = __floats2half2_rn(v.x, v.y);
        o2[idx * 2 + 1] = __floats2half2_rn(v.z, v.w);
    }
}

// batched centered weight transposes into WallTH
__global__ void __launch_bounds__(256)
transpose_w3(const float* __restrict__ Wq, const float* __restrict__ Wk,
             const float* __restrict__ Wv, const float* __restrict__ a,
             const float* __restrict__ b, const float* __restrict__ cv,
             __half* __restrict__ Wall, int R, int Cc)
{
    const int z = blockIdx.z;
    const float* in  = (z == 0) ? Wq : (z == 1) ? Wk : Wv;
    const float* ctr = (z == 0) ? a : (z == 1) ? b : cv;

    __shared__ float t[32][33];
    const int tx = threadIdx.x, ty = threadIdx.y;
    const int cx = blockIdx.x * 32 + tx;
    const float sub = ctr[cx];
#pragma unroll
    for (int i = 0; i < 4; i++) {
        int r = blockIdx.y * 32 + ty + i * 8;
        t[ty + i * 8][tx] = in[(size_t)r * Cc + cx] - sub;
    }
    __syncthreads();
    const int ox = blockIdx.y * 32 + tx;
    __half* O = Wall + (size_t)z * DOUT * DIN;
#pragma unroll
    for (int i = 0; i < 4; i++) {
        int oy = blockIdx.x * 32 + ty + i * 8;
        O[(size_t)oy * R + ox] = __float2half_rn(t[tx][ty + i * 8]);
    }
}

// single-pass softmax with MLP-4 loads: half unnorm P, invSum, tRow = sum exp*s
__global__ void __launch_bounds__(256)
softmax1t_kernel(const float* __restrict__ S, const unsigned* __restrict__ rowMaxKey,
                 const float* __restrict__ sRow,
                 __half* __restrict__ P, float* __restrict__ invSum,
                 float* __restrict__ tRow)
{
    __shared__ float sS[SEQ];
    __shared__ float red[256], redT[256];
    const int tid = threadIdx.x;
    {
        const float4* s4 = (const float4*)sRow;
        float4 a0 = s4[tid], a1 = s4[tid + 256], a2 = s4[tid + 512], a3 = s4[tid + 768];
        *(float4*)(sS + tid * 4)            = a0;
        *(float4*)(sS + (tid + 256) * 4)    = a1;
        *(float4*)(sS + (tid + 512) * 4)    = a2;
        *(float4*)(sS + (tid + 768) * 4)    = a3;
    }
    __syncthreads();

    const float4* p4 = (const float4*)(S + (size_t)blockIdx.x * SEQ);
    __half* q = P + (size_t)blockIdx.x * SEQ;
    const float m = funkey(rowMaxKey[blockIdx.x]);

    float4 v0 = p4[tid], v1 = p4[tid + 256], v2 = p4[tid + 512], v3 = p4[tid + 768];

    float sum = 0.0f, tsum = 0.0f;
#pragma unroll
    for (int u = 0; u < 4; u++) {
        float4 v = (u == 0) ? v0 : (u == 1) ? v1 : (u == 2) ? v2 : v3;
        const int c = (tid + u * 256) * 4;
        __half2 e0 = __floats2half2_rn(expf(v.x - m), expf(v.y - m));
        __half2 e1 = __floats2half2_rn(expf(v.z - m), expf(v.w - m));
        *(__half2*)(q + c)     = e0;
        *(__half2*)(q + c + 2) = e1;
        float2 f0 = __half22float2(e0), f1 = __half22float2(e1);
        sum  += f0.x + f0.y + f1.x + f1.y;
        tsum += f0.x * sS[c] + f0.y * sS[c + 1] + f1.x * sS[c + 2] + f1.y * sS[c + 3];
    }
    red[tid] = sum; redT[tid] = tsum; __syncthreads();
    for (int s = 128; s > 0; s >>= 1) {
        if (tid < s) { red[tid] += red[tid + s]; redT[tid] += redT[tid + s]; }
        __syncthreads();
    }
    if (tid == 0) {
        invSum[blockIdx.x] = 1.0f / red[0];
        tRow[blockIdx.x]   = redT[0];
    }
}

// ---------------------------------------------------------------------------
extern "C" void kernel_launch(void* const* d_in, const int* in_sizes, int n_in,
                              void* d_out, int out_size)
{
    const float* input = (const float*)d_in[0];
    const float* Wq    = (const float*)d_in[1];
    const float* Wk    = (const float*)d_in[2];
    const float* Wv    = (const float*)d_in[3];
    float*       out   = (float*)d_out;

    __half *inH, *WallTH, *QKVH, *PH;
    float *S, *invS, *tRow, *a, *b, *cv, *ab, *gq, *gk, *sRow, *colAdd, *zRow;
    unsigned* rowMax;
    cudaGetSymbolAddress((void**)&inH,    g_inH);
    cudaGetSymbolAddress((void**)&WallTH, g_WallTH);
    cudaGetSymbolAddress((void**)&QKVH,   g_QKVH);
    cudaGetSymbolAddress((void**)&S,      g_S);
    cudaGetSymbolAddress((void**)&PH,     g_PH);
    cudaGetSymbolAddress((void**)&invS,   g_invS);
    cudaGetSymbolAddress((void**)&tRow,   g_tRow);
    cudaGetSymbolAddress((void**)&a,      g_a);
    cudaGetSymbolAddress((void**)&b,      g_b);
    cudaGetSymbolAddress((void**)&cv,     g_cv);
    cudaGetSymbolAddress((void**)&ab,     g_ab);
    cudaGetSymbolAddress((void**)&gq,     g_gq);
    cudaGetSymbolAddress((void**)&gk,     g_gk);
    cudaGetSymbolAddress((void**)&sRow,   g_sRow);
    cudaGetSymbolAddress((void**)&colAdd, g_colAdd);
    cudaGetSymbolAddress((void**)&zRow,   g_zRow);
    cudaGetSymbolAddress((void**)&rowMax, g_rowMax);

    const int smemH  = NSTAGE_H * STAGEH_BYTES;   // 81920
    const int smemPV = NSTAGE_H * STAGE_PV;       // 75776
    cudaFuncSetAttribute(h16_gemm_h, cudaFuncAttributeMaxDynamicSharedMemorySize, smemH);
    cudaFuncSetAttribute(h16_scores, cudaFuncAttributeMaxDynamicSharedMemorySize, smemH);
    cudaFuncSetAttribute(h16_pv_nn,  cudaFuncAttributeMaxDynamicSharedMemorySize, smemPV);

    const float scale = 1.0f / 32.0f;   // 1/sqrt(1024)
    dim3 tb(32, 8);
    dim3 gQKV(3 * DOUT / 128, SEQ / 128);
    dim3 gProj(DOUT / 128, SEQ / 128);
    dim3 gS(SEQ / 128, SEQ / 128);

    // 1-5: rank-one machinery + staging
    colmean3<<<dim3(DOUT / 32, 3), 256>>>(Wq, Wk, Wv, a, b, cv);
    conv_h<<<SEQ * DIN / 16 / 256, 256>>>(input, inH, SEQ * DIN / 4, rowMax);
    dotab<<<1, 256>>>(a, b, ab);
    gvec<<<DIN, 256>>>(Wq, Wk, a, b, ab, gq, gk);
    transpose_w3<<<dim3(DOUT / 32, DIN / 32, 3), tb>>>(
        Wq, Wk, Wv, a, b, cv, WallTH, DIN, DOUT);

    // 6: combined QKV projection (profiled)
    h16_gemm_h<<<gQKV, 256, smemH>>>(inH, WallTH, QKVH, 3 * DOUT, DIN, DIN, DIN);

    // 7: correction vectors
    szvec<<<SEQ, 256>>>(input, gq, gk, ab, sRow, colAdd, zRow);

    // 8: scores = scale*(q~ k~^T + rank-3 correction), fused rowMax
    h16_scores<<<gS, 256, smemH>>>(QKVH, QKVH + DOUT, S, SEQ, DIN,
                                   3 * DOUT, 3 * DOUT,
                                   scale, sRow, colAdd, zRow, rowMax);

    // 9: softmax (single pass, MLP-4): P^, invSum, tRow
    softmax1t_kernel<<<SEQ, 256>>>(S, rowMax, sRow, PH, invS, tRow);

    // 10: out = invS * (P^ @ v~ + tRow * cv^T), NN-form B (no transpose needed)
    h16_pv_nn<<<gProj, 256, smemPV>>>(PH, QKVH + 2 * DOUT, out, DOUT, SEQ,
                                      SEQ, 3 * DOUT, invS, tRow, cv);
}

// round 15
// speedup vs baseline: 2.1212x; 1.0222x over previous
#include <cuda_runtime.h>
#include <cuda_fp16.h>
#include <math.h>
#include <stdint.h>

#define SEQ  4096
#define DIN  1024
#define DOUT 1024

// ---------------- scratch (__device__ globals, alloc-free rule) ----------------
__device__ __half g_inH[(size_t)SEQ * DIN];            // half(input)
__device__ __half g_WallH[(size_t)DIN * (3 * DOUT)];   // [W~q | W~k | W~v] centered, NN layout
__device__ __half g_QKVH[(size_t)SEQ * (3 * DOUT)];    // [q~ | k~ | v~] half
__device__ float  g_S[(size_t)SEQ * SEQ];              // fp32 scores
__device__ __half g_PH[(size_t)SEQ * SEQ];             // half unnorm probs
__device__ float  g_invS[SEQ];                         // 1/rowsum
__device__ float  g_tRow[SEQ];                         // sum_j exp_j * s_j
__device__ unsigned g_rowMax[SEQ];                     // monotone-keyed row max
__device__ float  g_a[DOUT], g_b[DOUT], g_cv[DOUT];    // col means of Wq, Wk, Wv
__device__ float  g_ab[1];                             // a . b
__device__ float  g_gqr[DIN], g_gkr[DIN];              // Wq b (raw), Wk a (raw)
__device__ float  g_sRow[SEQ];                         // s_i = rowsum(input)
__device__ float  g_colAdd[SEQ];                       // = in_i . gk_raw (exact identity)
__device__ float  g_zRow[SEQ];                         // = in_i . gq_raw - ab*s_i

#define KEY_NEG_INF 0x007FFFFFu

// ---------------- helpers ----------------
__device__ __forceinline__ unsigned fkey(float f) {
    unsigned b = __float_as_uint(f);
    return (b & 0x80000000u) ? ~b : (b | 0x80000000u);
}
__device__ __forceinline__ float funkey(unsigned k) {
    unsigned b = (k & 0x80000000u) ? (k & 0x7FFFFFFFu) : ~k;
    return __uint_as_float(b);
}
#define CP_ASYNC16(saddr, gaddr) \
    asm volatile("cp.async.cg.shared.global [%0], [%1], 16;" :: "r"(saddr), "l"(gaddr))
#define CP_COMMIT() asm volatile("cp.async.commit_group;" ::: "memory")
#define CP_WAIT_GROUP(n) asm volatile("cp.async.wait_group " #n ";" ::: "memory")

__device__ __forceinline__ uint32_t smem_u32(const void* p) {
    uint32_t a;
    asm("{ .reg .u64 t; cvta.to.shared.u64 t, %1; cvt.u32.u64 %0, t; }" : "=r"(a) : "l"(p));
    return a;
}
#define LDSM_X4(r0, r1, r2, r3, addr) \
    asm volatile("ldmatrix.sync.aligned.m8n8.x4.shared.b16 {%0,%1,%2,%3}, [%4];" \
                 : "=r"(r0), "=r"(r1), "=r"(r2), "=r"(r3) : "r"(addr))
#define LDSM_X4_T(r0, r1, r2, r3, addr) \
    asm volatile("ldmatrix.sync.aligned.m8n8.x4.trans.shared.b16 {%0,%1,%2,%3}, [%4];" \
                 : "=r"(r0), "=r"(r1), "=r"(r2), "=r"(r3) : "r"(addr))

__device__ __forceinline__ void mma_f16(float* d,
                                        uint32_t a0, uint32_t a1, uint32_t a2, uint32_t a3,
                                        uint32_t b0, uint32_t b1) {
    asm volatile("mma.sync.aligned.m16n8k16.row.col.f32.f16.f16.f32 "
                 "{%0,%1,%2,%3}, {%4,%5,%6,%7}, {%8,%9}, {%0,%1,%2,%3};"
                 : "+f"(d[0]), "+f"(d[1]), "+f"(d[2]), "+f"(d[3])
                 : "r"(a0), "r"(a1), "r"(a2), "r"(a3), "r"(b0), "r"(b1));
}

// ---------------- tile geometry ----------------
#define PADH 40
#define OPH_HALFS (128 * PADH)
#define OPH_BYTES (OPH_HALFS * 2)         // 10240
#define STAGEH_BYTES (2 * OPH_BYTES)      // 20480 (NT kernel: A + B)
#define NSTAGE_H 4
// NN B tile: 32 k-rows x 128 n, padded stride 136 halfs
#define PADB 136
#define OPB_BYTES (32 * PADB * 2)         // 8704
#define STAGE_NN (OPH_BYTES + OPB_BYTES)  // 18944

// ---- shared NN mainloop prolog (A NT-style rows, B [k][n] + ldmatrix.trans) ----
#define GEMM_NN_PROLOG()                                                           \
    extern __shared__ __half smh[];                                                \
    const uint32_t sbase = smem_u32(smh);                                          \
    const int gx = gridDim.x, gy = gridDim.y;                                      \
    const int lin = blockIdx.y * gx + blockIdx.x;                                  \
    const int GROUP = 8;                                                           \
    const int per = GROUP * gx;                                                    \
    const int g = lin / per;                                                       \
    const int rem = lin - g * per;                                                 \
    const int rowsLeft = gy - g * GROUP;                                           \
    const int rows = (GROUP < rowsLeft) ? GROUP : rowsLeft;                        \
    const int byi = g * GROUP + rem % rows;                                        \
    const int bxi = rem / rows;                                                    \
    const int tid  = threadIdx.x;                                                  \
    const int lane = tid & 31;                                                     \
    const int wid  = tid >> 5;                                                     \
    const int warpM = wid >> 2;                                                    \
    const int warpN = wid & 3;                                                     \
    const int gID  = lane >> 2;                                                    \
    const int tig  = lane & 3;                                                     \
    const int rowBase = byi * 128;                                                 \
    const int colBase = bxi * 128;                                                 \
    const int lt = lane >> 3;                                                      \
    const int l7 = lane & 7;                                                       \
    const int aOff  = ((lt & 1) * 8 + l7) * PADH + (lt >> 1) * 8;                  \
    const int bOffT = ((lt & 1) * 8 + l7) * PADB + (lt >> 1) * 8;                  \
    const int ldRow0 = tid >> 2;                                                   \
    const int ldSeg  = tid & 3;                                                    \
    const int bRow   = tid >> 4;                                                   \
    const int bSeg   = tid & 15;                                                   \
    auto load_stage = [&](int st, int k0) {                                        \
        const uint32_t sA = sbase + st * STAGE_NN;                                 \
        const uint32_t sB = sA + OPH_BYTES;                                        \
        _Pragma("unroll")                                                          \
        for (int i = 0; i < 2; i++) {                                              \
            const int row = ldRow0 + i * 64;                                       \
            CP_ASYNC16(sA + (row * PADH + ldSeg * 8) * 2,                          \
                       A + (size_t)(rowBase + row) * lda + k0 + ldSeg * 8);        \
        }                                                                          \
        _Pragma("unroll")                                                          \
        for (int i = 0; i < 2; i++) {                                              \
            const int row = bRow + i * 16;                                         \
            CP_ASYNC16(sB + (row * PADB + bSeg * 8) * 2,                           \
                       B + (size_t)(k0 + row) * ldb + colBase + bSeg * 8);         \
        }                                                                          \
    };                                                                             \
    float acc[4][4][4];                                                            \
    _Pragma("unroll")                                                              \
    for (int i = 0; i < 4; i++)                                                    \
        _Pragma("unroll")                                                          \
        for (int j = 0; j < 4; j++)                                                \
            _Pragma("unroll")                                                      \
            for (int r = 0; r < 4; r++) acc[i][j][r] = 0.0f;                       \
    const int NITER = Kd >> 5;                                                     \
    load_stage(0, 0);  CP_COMMIT();                                                \
    load_stage(1, 32); CP_COMMIT();                                                \
    load_stage(2, 64); CP_COMMIT();                                                \
    for (int j = 0; j < NITER; j++) {                                              \
        CP_WAIT_GROUP(2);                                                          \
        __syncthreads();                                                           \
        if (j + 3 < NITER) load_stage((j + 3) & 3, (j + 3) * 32);                  \
        CP_COMMIT();                                                               \
        const uint32_t sA = sbase + (j & 3) * STAGE_NN;                            \
        const uint32_t sB = sA + OPH_BYTES;                                        \
        _Pragma("unroll")                                                          \
        for (int s = 0; s < 2; s++) {                                              \
            uint32_t af[4][4];                                                     \
            _Pragma("unroll")                                                      \
            for (int i = 0; i < 4; i++) {                                          \
                const uint32_t addr = sA + (((warpM * 64 + i * 16) * PADH) + s * 16 + aOff) * 2; \
                LDSM_X4(af[i][0], af[i][1], af[i][2], af[i][3], addr);             \
            }                                                                      \
            uint32_t bf[4][2];                                                     \
            _Pragma("unroll")                                                      \
            for (int p = 0; p < 2; p++) {                                          \
                const uint32_t addr = sB +                                         \
                    ((s * 16) * PADB + warpN * 32 + p * 16 + bOffT) * 2;           \
                LDSM_X4_T(bf[2 * p][0], bf[2 * p][1], bf[2 * p + 1][0], bf[2 * p + 1][1], addr); \
            }                                                                      \
            _Pragma("unroll")                                                      \
            for (int i = 0; i < 4; i++)                                            \
                _Pragma("unroll")                                                  \
                for (int jn = 0; jn < 4; jn++)                                     \
                    mma_f16(acc[i][jn], af[i][0], af[i][1], af[i][2], af[i][3],    \
                            bf[jn][0], bf[jn][1]);                                 \
        }                                                                          \
    }

// ---- NT mainloop prolog (both operands K-major) for the scores kernel ----
#define GEMM_NT_PROLOG()                                                           \
    extern __shared__ __half smh[];                                                \
    const uint32_t sbase = smem_u32(smh);                                          \
    const int gx = gridDim.x, gy = gridDim.y;                                      \
    const int lin = blockIdx.y * gx + blockIdx.x;                                  \
    const int GROUP = 8;                                                           \
    const int per = GROUP * gx;                                                    \
    const int g = lin / per;                                                       \
    const int rem = lin - g * per;                                                 \
    const int rowsLeft = gy - g * GROUP;                                           \
    const int rows = (GROUP < rowsLeft) ? GROUP : rowsLeft;                        \
    const int byi = g * GROUP + rem % rows;                                        \
    const int bxi = rem / rows;                                                    \
    const int tid  = threadIdx.x;                                                  \
    const int lane = tid & 31;                                                     \
    const int wid  = tid >> 5;                                                     \
    const int warpM = wid >> 2;                                                    \
    const int warpN = wid & 3;                                                     \
    const int gID  = lane >> 2;                                                    \
    const int tig  = lane & 3;                                                     \
    const int rowBase = byi * 128;                                                 \
    const int colBase = bxi * 128;                                                 \
    const int lt = lane >> 3;                                                      \
    const int l7 = lane & 7;                                                       \
    const int aOff = ((lt & 1) * 8 + l7) * PADH + (lt >> 1) * 8;                   \
    const int bOff = ((lt >> 1) * 8 + l7) * PADH + (lt & 1) * 8;                   \
    const int ldRow0 = tid >> 2;                                                   \
    const int ldSeg  = tid & 3;                                                    \
    auto load_stage = [&](int st, int k0) {                                        \
        const uint32_t sA = sbase + st * STAGEH_BYTES;                             \
        const uint32_t sB = sA + OPH_BYTES;                                        \
        _Pragma("unroll")                                                          \
        for (int i = 0; i < 2; i++) {                                              \
            const int row = ldRow0 + i * 64;                                       \
            CP_ASYNC16(sA + (row * PADH + ldSeg * 8) * 2,                          \
                       A + (size_t)(rowBase + row) * lda + k0 + ldSeg * 8);        \
        }                                                                          \
        _Pragma("unroll")                                                          \
        for (int i = 0; i < 2; i++) {                                              \
            const int row = ldRow0 + i * 64;                                       \
            CP_ASYNC16(sB + (row * PADH + ldSeg * 8) * 2,                          \
                       B + (size_t)(colBase + row) * ldb + k0 + ldSeg * 8);        \
        }                                                                          \
    };                                                                             \
    float acc[4][4][4];                                                            \
    _Pragma("unroll")                                                              \
    for (int i = 0; i < 4; i++)                                                    \
        _Pragma("unroll")                                                          \
        for (int j = 0; j < 4; j++)                                                \
            _Pragma("unroll")                                                      \
            for (int r = 0; r < 4; r++) acc[i][j][r] = 0.0f;                       \
    const int NITER = Kd >> 5;                                                     \
    load_stage(0, 0);  CP_COMMIT();                                                \
    load_stage(1, 32); CP_COMMIT();                                                \
    load_stage(2, 64); CP_COMMIT();                                                \
    for (int j = 0; j < NITER; j++) {                                              \
        CP_WAIT_GROUP(2);                                                          \
        __syncthreads();                                                           \
        if (j + 3 < NITER) load_stage((j + 3) & 3, (j + 3) * 32);                  \
        CP_COMMIT();                                                               \
        const uint32_t sA = sbase + (j & 3) * STAGEH_BYTES;                        \
        const uint32_t sB = sA + OPH_BYTES;                                        \
        _Pragma("unroll")                                                          \
        for (int s = 0; s < 2; s++) {                                              \
            uint32_t af[4][4];                                                     \
            _Pragma("unroll")                                                      \
            for (int i = 0; i < 4; i++) {                                          \
                const uint32_t addr = sA + (((warpM * 64 + i * 16) * PADH) + s * 16 + aOff) * 2; \
                LDSM_X4(af[i][0], af[i][1], af[i][2], af[i][3], addr);             \
            }                                                                      \
            uint32_t bf[4][2];                                                     \
            _Pragma("unroll")                                                      \
            for (int p = 0; p < 2; p++) {                                          \
                const uint32_t addr = sB + (((warpN * 32 + p * 16) * PADH) + s * 16 + bOff) * 2; \
                LDSM_X4(bf[2 * p][0], bf[2 * p][1], bf[2 * p + 1][0], bf[2 * p + 1][1], addr);  \
            }                                                                      \
            _Pragma("unroll")                                                      \
            for (int i = 0; i < 4; i++)                                            \
                _Pragma("unroll")                                                  \
                for (int jn = 0; jn < 4; jn++)                                     \
                    mma_f16(acc[i][jn], af[i][0], af[i][1], af[i][2], af[i][3],    \
                            bf[jn][0], bf[jn][1]);                                 \
        }                                                                          \
    }

// ---------------------------------------------------------------------------
// QKV projection, NN form, half out: C = A @ B ; B = Wall [k, n], ldb = 3*DOUT
// ---------------------------------------------------------------------------
__global__ void __launch_bounds__(256, 2)
h16_qkv_nn(const __half* __restrict__ A, const __half* __restrict__ B,
           __half* __restrict__ Cv, int Ntot, int Kd, int lda, int ldb)
{
    GEMM_NN_PROLOG()

#pragma unroll
    for (int i = 0; i < 4; i++) {
        const int r0 = rowBase + warpM * 64 + i * 16 + gID;
#pragma unroll
        for (int jn = 0; jn < 4; jn++) {
            const int c = colBase + warpN * 32 + jn * 8 + tig * 2;
#pragma unroll
            for (int half = 0; half < 2; half++) {
                const int r = r0 + half * 8;
                __half2 h = __floats2half2_rn(acc[i][jn][half * 2 + 0],
                                              acc[i][jn][half * 2 + 1]);
                *(__half2*)(Cv + (size_t)r * Ntot + c) = h;
            }
        }
    }
}

// ---------------------------------------------------------------------------
// scores GEMM (NT): S = scale*(q~ k~^T + s_i*colAdd_j + z_i*s_j), fused rowMax
// ---------------------------------------------------------------------------
__global__ void __launch_bounds__(256, 2)
h16_scores(const __half* __restrict__ A, const __half* __restrict__ B,
           float* __restrict__ Cv, int Ntot, int Kd, int lda, int ldb,
           float scale, const float* __restrict__ sRow,
           const float* __restrict__ colAdd, const float* __restrict__ zRow,
           unsigned* __restrict__ rowMax)
{
    GEMM_NT_PROLOG()

#pragma unroll
    for (int i = 0; i < 4; i++) {
        const int r0 = rowBase + warpM * 64 + i * 16 + gID;
#pragma unroll
        for (int half = 0; half < 2; half++) {
            const int r = r0 + half * 8;
            const float sr = sRow[r];
            const float zr = zRow[r];
            float vmax = -INFINITY;
#pragma unroll
            for (int jn = 0; jn < 4; jn++) {
                const int c = colBase + warpN * 32 + jn * 8 + tig * 2;
                float2 v;
                v.x = scale * (acc[i][jn][half * 2 + 0] + sr * colAdd[c]     + zr * sRow[c]);
                v.y = scale * (acc[i][jn][half * 2 + 1] + sr * colAdd[c + 1] + zr * sRow[c + 1]);
                *(float2*)(Cv + (size_t)r * Ntot + c) = v;
                vmax = fmaxf(vmax, fmaxf(v.x, v.y));
            }
            vmax = fmaxf(vmax, __shfl_xor_sync(0xFFFFFFFFu, vmax, 1));
            vmax = fmaxf(vmax, __shfl_xor_sync(0xFFFFFFFFu, vmax, 2));
            if (tig == 0) atomicMax(rowMax + r, fkey(vmax));
        }
    }
}

// ---------------------------------------------------------------------------
// PV GEMM, NN form: out = invS[r]*(P^ @ B + tRow[r]*cv[c]); B = v~ [j, d]
// ---------------------------------------------------------------------------
__global__ void __launch_bounds__(256, 2)
h16_pv_nn(const __half* __restrict__ A, const __half* __restrict__ B,
          float* __restrict__ Cv, int Ntot, int Kd, int lda, int ldb,
          const float* __restrict__ invS, const float* __restrict__ tRow,
          const float* __restrict__ cvec)
{
    GEMM_NN_PROLOG()

#pragma unroll
    for (int i = 0; i < 4; i++) {
        const int r0 = rowBase + warpM * 64 + i * 16 + gID;
#pragma unroll
        for (int jn = 0; jn < 4; jn++) {
            const int c = colBase + warpN * 32 + jn * 8 + tig * 2;
#pragma unroll
            for (int half = 0; half < 2; half++) {
                const int r = r0 + half * 8;
                const float sc = invS[r];
                const float tr = tRow[r];
                float2 v;
                v.x = sc * (acc[i][jn][half * 2 + 0] + tr * cvec[c]);
                v.y = sc * (acc[i][jn][half * 2 + 1] + tr * cvec[c + 1]);
                *(float2*)(Cv + (size_t)r * Ntot + c) = v;
            }
        }
    }
}

// ---------------------------------------------------------------------------
// column means of Wq, Wk, Wv -> a, b, cv
// ---------------------------------------------------------------------------
__global__ void __launch_bounds__(256)
colmean3(const float* __restrict__ Wq, const float* __restrict__ Wk,
         const float* __restrict__ Wv,
         float* __restrict__ a, float* __restrict__ b, float* __restrict__ cv)
{
    const float* W = (blockIdx.y == 0) ? Wq : (blockIdx.y == 1) ? Wk : Wv;
    float* o       = (blockIdx.y == 0) ? a  : (blockIdx.y == 1) ? b  : cv;
    __shared__ float red[8][33];
    const int tx = threadIdx.x & 31, ty = threadIdx.x >> 5;
    const int col = blockIdx.x * 32 + tx;
    float acc = 0.0f;
    for (int r = ty; r < DIN; r += 8)
        acc += W[(size_t)r * DOUT + col];
    red[ty][tx] = acc;
    __syncthreads();
    if (ty == 0) {
        float s = 0.0f;
#pragma unroll
        for (int k = 0; k < 8; k++) s += red[k][tx];
        o[col] = s * (1.0f / DIN);
    }
}

// a . b
__global__ void __launch_bounds__(256)
dotab(const float* __restrict__ a, const float* __restrict__ b, float* __restrict__ ab)
{
    __shared__ float red[256];
    float p = 0.0f;
    for (int i = threadIdx.x; i < DOUT; i += 256) p += a[i] * b[i];
    red[threadIdx.x] = p; __syncthreads();
    for (int s = 128; s > 0; s >>= 1) { if (threadIdx.x < s) red[threadIdx.x] += red[threadIdx.x + s]; __syncthreads(); }
    if (threadIdx.x == 0) ab[0] = red[0];
}

// RAW g-vectors via float4 (1 vectorized sweep): gqr_c = Wq[c,:].b, gkr_c = Wk[c,:].a
__global__ void __launch_bounds__(256)
gvec_raw(const float* __restrict__ Wq, const float* __restrict__ Wk,
         const float* __restrict__ a, const float* __restrict__ b,
         float* __restrict__ gqr, float* __restrict__ gkr)
{
    __shared__ float r1[256], r2[256];
    const int c = blockIdx.x;
    const int t = threadIdx.x;
    const float4 wq = ((const float4*)(Wq + (size_t)c * DOUT))[t];
    const float4 wk = ((const float4*)(Wk + (size_t)c * DOUT))[t];
    const float4 bv = ((const float4*)b)[t];
    const float4 av = ((const float4*)a)[t];
    float pq = wq.x * bv.x + wq.y * bv.y + wq.z * bv.z + wq.w * bv.w;
    float pk = wk.x * av.x + wk.y * av.y + wk.z * av.z + wk.w * av.w;
    r1[t] = pq; r2[t] = pk; __syncthreads();
    for (int s = 128; s > 0; s >>= 1) {
        if (t < s) { r1[t] += r1[t + s]; r2[t] += r2[t + s]; }
        __syncthreads();
    }
    if (t == 0) { gqr[c] = r1[0]; gkr[c] = r2[0]; }
}

// per input row i (float4, 1 sweep): s_i, colAdd_i = in.gkr, zRow_i = in.gqr - ab*s_i
__global__ void __launch_bounds__(256)
szvec(const float* __restrict__ in, const float* __restrict__ gqr,
      const float* __restrict__ gkr, const float* __restrict__ ab,
      float* __restrict__ sRow, float* __restrict__ colAdd, float* __restrict__ zRow)
{
    __shared__ float r1[256], r2[256], r3[256];
    const int i = blockIdx.x;
    const int t = threadIdx.x;
    const float4 v  = ((const float4*)(in + (size_t)i * DIN))[t];
    const float4 q4 = ((const float4*)gqr)[t];
    const float4 k4 = ((const float4*)gkr)[t];
    float s = v.x + v.y + v.z + v.w;
    float z = v.x * q4.x + v.y * q4.y + v.z * q4.z + v.w * q4.w;
    float w = v.x * k4.x + v.y * k4.y + v.z * k4.z + v.w * k4.w;
    r1[t] = s; r2[t] = z; r3[t] = w; __syncthreads();
    for (int st = 128; st > 0; st >>= 1) {
        if (t < st) { r1[t] += r1[t + st]; r2[t] += r2[t + st]; r3[t] += r3[t + st]; }
        __syncthreads();
    }
    if (t == 0) {
        sRow[i]   = r1[0];
        zRow[i]   = r2[0] - ab[0] * r1[0];
        colAdd[i] = r3[0];
    }
}

// f32 -> half convert, MLP-4; inits rowMax
__global__ void __launch_bounds__(256)
conv_h(const float* __restrict__ in, __half* __restrict__ out,
       unsigned* __restrict__ rowMax)
{
    const int t = blockIdx.x * 256 + threadIdx.x;
    const int chunk = gridDim.x * 256;
    if (t < SEQ) rowMax[t] = KEY_NEG_INF;
    const float4* in4 = (const float4*)in;
    float4 v0 = in4[t];
    float4 v1 = in4[t + chunk];
    float4 v2 = in4[t + 2 * chunk];
    float4 v3 = in4[t + 3 * chunk];
    __half2* o2 = (__half2*)out;
#pragma unroll
    for (int u = 0; u < 4; u++) {
        float4 v = (u == 0) ? v0 : (u == 1) ? v1 : (u == 2) ? v2 : v3;
        const int idx = t + u * chunk;
        o2[idx * 2]     = __floats2half2_rn(v.x, v.y);
        o2[idx * 2 + 1] = __floats2half2_rn(v.z, v.w);
    }
}

// center + convert W into NN layout: Wall[k, z*DOUT + d] = Wz[k,d] - ctr_z[d]
__global__ void __launch_bounds__(256)
center_w(const float* __restrict__ Wq, const float* __restrict__ Wk,
         const float* __restrict__ Wv, const float* __restrict__ a,
         const float* __restrict__ b, const float* __restrict__ cv,
         __half* __restrict__ Wall)
{
    const int z = blockIdx.y;
    const float* W   = (z == 0) ? Wq : (z == 1) ? Wk : Wv;
    const float* ctr = (z == 0) ? a : (z == 1) ? b : cv;

    const int idx = blockIdx.x * 256 + threadIdx.x;   // float4 index over [DIN*DOUT/4)
    const int k  = idx >> 8;                          // DOUT/4 = 256 float4 per row
    const int d4 = idx & 255;
    float4 w = ((const float4*)(W + (size_t)k * DOUT))[d4];
    float4 c = ((const float4*)ctr)[d4];
    __half2 h0 = __floats2half2_rn(w.x - c.x, w.y - c.y);
    __half2 h1 = __floats2half2_rn(w.z - c.z, w.w - c.w);
    __half* row = Wall + (size_t)k * (3 * DOUT) + z * DOUT + d4 * 4;
    *(__half2*)(row)     = h0;
    *(__half2*)(row + 2) = h1;
}

// single-pass softmax with MLP-4 loads: half unnorm P, invSum, tRow = sum exp*s
__global__ void __launch_bounds__(256)
softmax1t_kernel(const float* __restrict__ S, const unsigned* __restrict__ rowMaxKey,
                 const float* __restrict__ sRow,
                 __half* __restrict__ P, float* __restrict__ invSum,
                 float* __restrict__ tRow)
{
    __shared__ float sS[SEQ];
    __shared__ float red[256], redT[256];
    const int tid = threadIdx.x;
    {
        const float4* s4 = (const float4*)sRow;
        float4 a0 = s4[tid], a1 = s4[tid + 256], a2 = s4[tid + 512], a3 = s4[tid + 768];
        *(float4*)(sS + tid * 4)         = a0;
        *(float4*)(sS + (tid + 256) * 4) = a1;
        *(float4*)(sS + (tid + 512) * 4) = a2;
        *(float4*)(sS + (tid + 768) * 4) = a3;
    }
    __syncthreads();

    const float4* p4 = (const float4*)(S + (size_t)blockIdx.x * SEQ);
    __half* q = P + (size_t)blockIdx.x * SEQ;
    const float m = funkey(rowMaxKey[blockIdx.x]);

    float4 v0 = p4[tid], v1 = p4[tid + 256], v2 = p4[tid + 512], v3 = p4[tid + 768];

    float sum = 0.0f, tsum = 0.0f;
#pragma unroll
    for (int u = 0; u < 4; u++) {
        float4 v = (u == 0) ? v0 : (u == 1) ? v1 : (u == 2) ? v2 : v3;
        const int c = (tid + u * 256) * 4;
        __half2 e0 = __floats2half2_rn(expf(v.x - m), expf(v.y - m));
        __half2 e1 = __floats2half2_rn(expf(v.z - m), expf(v.w - m));
        *(__half2*)(q + c)     = e0;
        *(__half2*)(q + c + 2) = e1;
        float2 f0 = __half22float2(e0), f1 = __half22float2(e1);
        sum  += f0.x + f0.y + f1.x + f1.y;
        tsum += f0.x * sS[c] + f0.y * sS[c + 1] + f1.x * sS[c + 2] + f1.y * sS[c + 3];
    }
    red[tid] = sum; redT[tid] = tsum; __syncthreads();
    for (int s = 128; s > 0; s >>= 1) {
        if (tid < s) { red[tid] += red[tid + s]; redT[tid] += redT[tid + s]; }
        __syncthreads();
    }
    if (tid == 0) {
        invSum[blockIdx.x] = 1.0f / red[0];
        tRow[blockIdx.x]   = redT[0];
    }
}

// ---------------------------------------------------------------------------
extern "C" void kernel_launch(void* const* d_in, const int* in_sizes, int n_in,
                              void* d_out, int out_size)
{
    const float* input = (const float*)d_in[0];
    const float* Wq    = (const float*)d_in[1];
    const float* Wk    = (const float*)d_in[2];
    const float* Wv    = (const float*)d_in[3];
    float*       out   = (float*)d_out;

    __half *inH, *WallH, *QKVH, *PH;
    float *S, *invS, *tRow, *a, *b, *cv, *ab, *gqr, *gkr, *sRow, *colAdd, *zRow;
    unsigned* rowMax;
    cudaGetSymbolAddress((void**)&inH,    g_inH);
    cudaGetSymbolAddress((void**)&WallH,  g_WallH);
    cudaGetSymbolAddress((void**)&QKVH,   g_QKVH);
    cudaGetSymbolAddress((void**)&S,      g_S);
    cudaGetSymbolAddress((void**)&PH,     g_PH);
    cudaGetSymbolAddress((void**)&invS,   g_invS);
    cudaGetSymbolAddress((void**)&tRow,   g_tRow);
    cudaGetSymbolAddress((void**)&a,      g_a);
    cudaGetSymbolAddress((void**)&b,      g_b);
    cudaGetSymbolAddress((void**)&cv,     g_cv);
    cudaGetSymbolAddress((void**)&ab,     g_ab);
    cudaGetSymbolAddress((void**)&gqr,    g_gqr);
    cudaGetSymbolAddress((void**)&gkr,    g_gkr);
    cudaGetSymbolAddress((void**)&sRow,   g_sRow);
    cudaGetSymbolAddress((void**)&colAdd, g_colAdd);
    cudaGetSymbolAddress((void**)&zRow,   g_zRow);
    cudaGetSymbolAddress((void**)&rowMax, g_rowMax);

    const int smemNT = NSTAGE_H * STAGEH_BYTES;   // 81920
    const int smemNN = NSTAGE_H * STAGE_NN;       // 75776
    cudaFuncSetAttribute(h16_qkv_nn, cudaFuncAttributeMaxDynamicSharedMemorySize, smemNN);
    cudaFuncSetAttribute(h16_scores, cudaFuncAttributeMaxDynamicSharedMemorySize, smemNT);
    cudaFuncSetAttribute(h16_pv_nn,  cudaFuncAttributeMaxDynamicSharedMemorySize, smemNN);

    const float scale = 1.0f / 32.0f;   // 1/sqrt(1024)
    dim3 gQKV(3 * DOUT / 128, SEQ / 128);
    dim3 gProj(DOUT / 128, SEQ / 128);
    dim3 gS(SEQ / 128, SEQ / 128);

    // 1-5: rank-one machinery + staging
    colmean3<<<dim3(DOUT / 32, 3), 256>>>(Wq, Wk, Wv, a, b, cv);
    conv_h<<<SEQ * DIN / 16 / 256, 256>>>(input, inH, rowMax);
    dotab<<<1, 256>>>(a, b, ab);
    gvec_raw<<<DIN, 256>>>(Wq, Wk, a, b, gqr, gkr);
    center_w<<<dim3(DIN * DOUT / 4 / 256, 3), 256>>>(Wq, Wk, Wv, a, b, cv, WallH);

    // 6: combined QKV projection, NN form (profiled)
    h16_qkv_nn<<<gQKV, 256, smemNN>>>(inH, WallH, QKVH, 3 * DOUT, DIN,
                                      DIN, 3 * DOUT);

    // 7: correction vectors (simplified identities)
    szvec<<<SEQ, 256>>>(input, gqr, gkr, ab, sRow, colAdd, zRow);

    // 8: scores = scale*(q~ k~^T + rank-3 correction), fused rowMax
    h16_scores<<<gS, 256, smemNT>>>(QKVH, QKVH + DOUT, S, SEQ, DIN,
                                    3 * DOUT, 3 * DOUT,
                                    scale, sRow, colAdd, zRow, rowMax);

    // 9: softmax (single pass, MLP-4): P^, invSum, tRow
    softmax1t_kernel<<<SEQ, 256>>>(S, rowMax, sRow, PH, invS, tRow);

    // 10: out = invS * (P^ @ v~ + tRow * cv^T), NN form
    h16_pv_nn<<<gProj, 256, smemNN>>>(PH, QKVH + 2 * DOUT, out, DOUT, SEQ,
                                      SEQ, 3 * DOUT, invS, tRow, cv);
}